// round 4
// baseline (speedup 1.0000x reference)
#include <cuda_runtime.h>
#include <math.h>

// Problem constants
#define BATCH 32
#define SEQ   2048
#define CDIM  384
#define HDIM  64
#define BT    (BATCH * SEQ)

// Scratch for projected q,k,v: 3 x 16.8 MB, static device globals (allocation-free rule)
__device__ float g_q[BT * HDIM];
__device__ float g_k[BT * HDIM];
__device__ float g_v[BT * HDIM];

// ---------------------------------------------------------------------------
// Kernel 1: fused QKV projection.  out = x @ W for W in {Wq, Wk, Wv}.
// One pass over x. Block: 64 rows x (3 x 64) cols, 256 threads, 4x4 reg tiles.
// ---------------------------------------------------------------------------
__global__ __launch_bounds__(256) void qkv_proj_kernel(
    const float* __restrict__ x,
    const float* __restrict__ Wk,
    const float* __restrict__ Wq,
    const float* __restrict__ Wv)
{
    __shared__ float xs[32][64 + 4];     // x tile, transposed [k][row]
    __shared__ float ws[3][32][64];      // weight tiles [mat][k][h]

    const int m0 = blockIdx.x * 64;
    const int t  = threadIdx.x;
    const int tx = t & 15;               // col group (16)
    const int ty = t >> 4;               // row group (16)

    float acc[3][4][4];
    #pragma unroll
    for (int mm = 0; mm < 3; mm++)
        #pragma unroll
        for (int i = 0; i < 4; i++)
            #pragma unroll
            for (int j = 0; j < 4; j++)
                acc[mm][i][j] = 0.f;

    const float* Wmat[3] = {Wq, Wk, Wv};

    for (int k0 = 0; k0 < CDIM; k0 += 32) {
        // Load x tile (64 rows x 32 cols), store transposed.
        #pragma unroll
        for (int rep = 0; rep < 2; rep++) {
            int id = t + rep * 256;          // 0..511, 512 float4s
            int r  = id >> 3;                // 0..63
            int c4 = (id & 7) * 4;           // 0..28
            float4 v = *(const float4*)(x + (size_t)(m0 + r) * CDIM + k0 + c4);
            xs[c4 + 0][r] = v.x;
            xs[c4 + 1][r] = v.y;
            xs[c4 + 2][r] = v.z;
            xs[c4 + 3][r] = v.w;
        }
        // Load 3 weight tiles (32 x 64 each).
        #pragma unroll
        for (int mm = 0; mm < 3; mm++) {
            #pragma unroll
            for (int rep = 0; rep < 2; rep++) {
                int id = t + rep * 256;      // 0..511
                int kk = id >> 4;            // 0..31
                int h4 = (id & 15) * 4;      // 0..60
                float4 v = *(const float4*)(Wmat[mm] + (size_t)(k0 + kk) * HDIM + h4);
                *(float4*)&ws[mm][kk][h4] = v;
            }
        }
        __syncthreads();

        #pragma unroll 8
        for (int kk = 0; kk < 32; kk++) {
            float a[4];
            #pragma unroll
            for (int i = 0; i < 4; i++) a[i] = xs[kk][ty * 4 + i];
            #pragma unroll
            for (int mm = 0; mm < 3; mm++) {
                float4 bv = *(const float4*)&ws[mm][kk][tx * 4];
                #pragma unroll
                for (int i = 0; i < 4; i++) {
                    acc[mm][i][0] += a[i] * bv.x;
                    acc[mm][i][1] += a[i] * bv.y;
                    acc[mm][i][2] += a[i] * bv.z;
                    acc[mm][i][3] += a[i] * bv.w;
                }
            }
        }
        __syncthreads();
    }

    float* outp[3] = {g_q, g_k, g_v};
    #pragma unroll
    for (int mm = 0; mm < 3; mm++) {
        #pragma unroll
        for (int i = 0; i < 4; i++) {
            float4 v = make_float4(acc[mm][i][0], acc[mm][i][1],
                                   acc[mm][i][2], acc[mm][i][3]);
            *(float4*)(outp[mm] + (size_t)(m0 + ty * 4 + i) * HDIM + tx * 4) = v;
        }
    }
}

// ---------------------------------------------------------------------------
// Kernel 2: causal flash attention. Block = 128 query rows (one row/thread),
// K/V tiles of 64 in shared, scores in 32-wide register chunks with online
// softmax. Grid: (T/128, B).
// ---------------------------------------------------------------------------
__global__ __launch_bounds__(128) void attn_kernel(float* __restrict__ out)
{
    __shared__ float ks[64][64];
    __shared__ float vs[64][64];

    const int b   = blockIdx.y;
    const int qt  = blockIdx.x;
    const int tid = threadIdx.x;
    const int r   = qt * 128 + tid;          // global query row within batch
    const float scale = 0.125f;              // H^{-1/2}, H=64

    // q row in registers (pre-scaled)
    float q[HDIM];
    {
        const float* qptr = g_q + ((size_t)b * SEQ + r) * HDIM;
        #pragma unroll
        for (int h = 0; h < HDIM; h += 4) {
            float4 v = *(const float4*)(qptr + h);
            q[h + 0] = v.x * scale;
            q[h + 1] = v.y * scale;
            q[h + 2] = v.z * scale;
            q[h + 3] = v.w * scale;
        }
    }

    float O[HDIM];
    #pragma unroll
    for (int h = 0; h < HDIM; h++) O[h] = 0.f;
    float m = -INFINITY;
    float l = 0.f;

    const int nkt = (qt + 1) * 2;            // number of 64-wide key tiles needed

    for (int kt = 0; kt < nkt; kt++) {
        const int j0 = kt * 64;
        const float* kptr = g_k + ((size_t)b * SEQ + j0) * HDIM;
        const float* vptr = g_v + ((size_t)b * SEQ + j0) * HDIM;

        __syncthreads();                     // previous tile fully consumed
        for (int i = tid; i < 64 * 16; i += 128) {
            int row = i >> 4;
            int h4  = (i & 15) * 4;
            *(float4*)&ks[row][h4] = *(const float4*)(kptr + (size_t)row * HDIM + h4);
            *(float4*)&vs[row][h4] = *(const float4*)(vptr + (size_t)row * HDIM + h4);
        }
        __syncthreads();

        // two 32-key chunks: keeps score registers at 32
        #pragma unroll
        for (int half = 0; half < 2; half++) {
            const int jb = half * 32;
            float s[32];
            float mt = -INFINITY;

            #pragma unroll
            for (int j = 0; j < 32; j++) {
                float a0 = 0.f, a1 = 0.f, a2 = 0.f, a3 = 0.f;
                #pragma unroll
                for (int h = 0; h < HDIM; h += 4) {
                    float4 kv = *(const float4*)&ks[jb + j][h];
                    a0 += q[h + 0] * kv.x;
                    a1 += q[h + 1] * kv.y;
                    a2 += q[h + 2] * kv.z;
                    a3 += q[h + 3] * kv.w;
                }
                float acc = (a0 + a1) + (a2 + a3);
                acc = (j0 + jb + j <= r) ? acc : -INFINITY;
                s[j] = acc;
                mt = fmaxf(mt, acc);
            }

            const float mn   = fmaxf(m, mt);
            const float corr = __expf(m - mn);   // 0 on first chunk (m=-inf)
            l *= corr;
            #pragma unroll
            for (int h = 0; h < HDIM; h++) O[h] *= corr;

            #pragma unroll
            for (int j = 0; j < 32; j++) {
                float p = __expf(s[j] - mn);
                l += p;
                #pragma unroll
                for (int h = 0; h < HDIM; h += 4) {
                    float4 vv = *(const float4*)&vs[jb + j][h];
                    O[h + 0] += p * vv.x;
                    O[h + 1] += p * vv.y;
                    O[h + 2] += p * vv.z;
                    O[h + 3] += p * vv.w;
                }
            }
            m = mn;
        }
    }

    const float inv = 1.f / l;
    float* optr = out + ((size_t)b * SEQ + r) * HDIM;
    #pragma unroll
    for (int h = 0; h < HDIM; h += 4) {
        float4 v = make_float4(O[h] * inv, O[h + 1] * inv,
                               O[h + 2] * inv, O[h + 3] * inv);
        *(float4*)(optr + h) = v;
    }
}

// ---------------------------------------------------------------------------
extern "C" void kernel_launch(void* const* d_in, const int* in_sizes, int n_in,
                              void* d_out, int out_size)
{
    const float* x  = (const float*)d_in[0];
    const float* Wk = (const float*)d_in[1];
    const float* Wq = (const float*)d_in[2];
    const float* Wv = (const float*)d_in[3];
    float* out = (float*)d_out;

    (void)in_sizes; (void)n_in; (void)out_size;

    qkv_proj_kernel<<<BT / 64, 256>>>(x, Wk, Wq, Wv);
    attn_kernel<<<dim3(SEQ / 128, BATCH), 128>>>(out);
}

// round 8
// speedup vs baseline: 3.9965x; 3.9965x over previous
#include <cuda_runtime.h>
#include <cuda_fp16.h>
#include <math.h>
#include <stdint.h>

// Problem constants
#define BATCH 32
#define SEQ   2048
#define CDIM  384
#define HDIM  64
#define BT    (BATCH * SEQ)

// Projected q,k,v stored as fp16 hi/lo split pairs (value = hi + lo, ~22-bit precision)
__device__ __half g_qh[BT * HDIM];
__device__ __half g_ql[BT * HDIM];
__device__ __half g_kh[BT * HDIM];
__device__ __half g_kl[BT * HDIM];
__device__ __half g_vh[BT * HDIM];
__device__ __half g_vl[BT * HDIM];

// ===========================================================================
// Warp-MMA helpers (sm_80+ baseline PTX: no 'a'-suffix features needed)
// ===========================================================================
__device__ __forceinline__ uint32_t smem_u32(const void* p) {
    uint32_t a;
    asm("{ .reg .u64 t; cvta.to.shared.u64 t, %1; cvt.u32.u64 %0, t; }"
        : "=r"(a) : "l"(p));
    return a;
}

__device__ __forceinline__ void ldsm_x4(uint32_t* r, uint32_t a) {
    asm volatile("ldmatrix.sync.aligned.m8n8.x4.shared.b16 {%0,%1,%2,%3}, [%4];"
                 : "=r"(r[0]), "=r"(r[1]), "=r"(r[2]), "=r"(r[3]) : "r"(a));
}
__device__ __forceinline__ void ldsm_x4_t(uint32_t* r, uint32_t a) {
    asm volatile("ldmatrix.sync.aligned.m8n8.x4.trans.shared.b16 {%0,%1,%2,%3}, [%4];"
                 : "=r"(r[0]), "=r"(r[1]), "=r"(r[2]), "=r"(r[3]) : "r"(a));
}

__device__ __forceinline__ void mma_f16(float* c, const uint32_t* a,
                                        uint32_t b0, uint32_t b1) {
    asm volatile(
        "mma.sync.aligned.m16n8k16.row.col.f32.f16.f16.f32 "
        "{%0,%1,%2,%3}, {%4,%5,%6,%7}, {%8,%9}, {%0,%1,%2,%3};"
        : "+f"(c[0]), "+f"(c[1]), "+f"(c[2]), "+f"(c[3])
        : "r"(a[0]), "r"(a[1]), "r"(a[2]), "r"(a[3]), "r"(b0), "r"(b1));
}

__device__ __forceinline__ uint32_t pack_h2(__half x, __half y) {
    __half2 t = __halves2half2(x, y);
    return *(uint32_t*)&t;
}

// Split a float pair into packed fp16 hi and lo words.
__device__ __forceinline__ void split_pair(float x, float y,
                                           uint32_t& hi, uint32_t& lo) {
    __half hx = __float2half(x);
    __half hy = __float2half(y);
    __half lx = __float2half(x - __half2float(hx));
    __half ly = __float2half(y - __half2float(hy));
    hi = pack_h2(hx, hy);
    lo = pack_h2(lx, ly);
}

// ---------------------------------------------------------------------------
// Kernel 1: fused QKV projection (fp32 GEMM, known-good), epilogue now emits
// fp16 hi/lo split arrays; q is pre-scaled by H^{-1/2}.
// ---------------------------------------------------------------------------
__global__ __launch_bounds__(256) void qkv_proj_kernel(
    const float* __restrict__ x,
    const float* __restrict__ Wk,
    const float* __restrict__ Wq,
    const float* __restrict__ Wv)
{
    __shared__ float xs[32][64 + 4];
    __shared__ float ws[3][32][64];

    const int m0 = blockIdx.x * 64;
    const int t  = threadIdx.x;
    const int tx = t & 15;
    const int ty = t >> 4;

    float acc[3][4][4];
    #pragma unroll
    for (int mm = 0; mm < 3; mm++)
        #pragma unroll
        for (int i = 0; i < 4; i++)
            #pragma unroll
            for (int j = 0; j < 4; j++)
                acc[mm][i][j] = 0.f;

    const float* Wmat[3] = {Wq, Wk, Wv};

    for (int k0 = 0; k0 < CDIM; k0 += 32) {
        #pragma unroll
        for (int rep = 0; rep < 2; rep++) {
            int id = t + rep * 256;
            int r  = id >> 3;
            int c4 = (id & 7) * 4;
            float4 v = *(const float4*)(x + (size_t)(m0 + r) * CDIM + k0 + c4);
            xs[c4 + 0][r] = v.x;
            xs[c4 + 1][r] = v.y;
            xs[c4 + 2][r] = v.z;
            xs[c4 + 3][r] = v.w;
        }
        #pragma unroll
        for (int mm = 0; mm < 3; mm++) {
            #pragma unroll
            for (int rep = 0; rep < 2; rep++) {
                int id = t + rep * 256;
                int kk = id >> 4;
                int h4 = (id & 15) * 4;
                float4 v = *(const float4*)(Wmat[mm] + (size_t)(k0 + kk) * HDIM + h4);
                *(float4*)&ws[mm][kk][h4] = v;
            }
        }
        __syncthreads();

        #pragma unroll 8
        for (int kk = 0; kk < 32; kk++) {
            float a[4];
            #pragma unroll
            for (int i = 0; i < 4; i++) a[i] = xs[kk][ty * 4 + i];
            #pragma unroll
            for (int mm = 0; mm < 3; mm++) {
                float4 bv = *(const float4*)&ws[mm][kk][tx * 4];
                #pragma unroll
                for (int i = 0; i < 4; i++) {
                    acc[mm][i][0] += a[i] * bv.x;
                    acc[mm][i][1] += a[i] * bv.y;
                    acc[mm][i][2] += a[i] * bv.z;
                    acc[mm][i][3] += a[i] * bv.w;
                }
            }
        }
        __syncthreads();
    }

    __half* oh[3] = {g_qh, g_kh, g_vh};
    __half* ol[3] = {g_ql, g_kl, g_vl};
    const float scl[3] = {0.125f, 1.f, 1.f};   // fold H^{-1/2} into q

    #pragma unroll
    for (int mm = 0; mm < 3; mm++) {
        #pragma unroll
        for (int i = 0; i < 4; i++) {
            float v0 = acc[mm][i][0] * scl[mm];
            float v1 = acc[mm][i][1] * scl[mm];
            float v2 = acc[mm][i][2] * scl[mm];
            float v3 = acc[mm][i][3] * scl[mm];
            uint32_t h01, l01, h23, l23;
            split_pair(v0, v1, h01, l01);
            split_pair(v2, v3, h23, l23);
            size_t off = (size_t)(m0 + ty * 4 + i) * HDIM + tx * 4;
            *(uint2*)(oh[mm] + off) = make_uint2(h01, h23);
            *(uint2*)(ol[mm] + off) = make_uint2(l01, l23);
        }
    }
}

// ---------------------------------------------------------------------------
// Kernel 2: warp-MMA flash attention (HMMA fallback path).
// Block: 256 threads / 8 warps, 128 q-rows (16 per warp), 64-key tiles.
// S = Qh.Kh + Qh.Kl + Ql.Kh ; P split in-register ; O += Ph.Vh + Ph.Vl + Pl.Vh.
// Smem: 4 x [64x64] half tiles (Kh,Kl,Vh,Vl), XOR-swizzled rows; Q staged
// through the same buffer before the loop (fragments persist in registers).
// ---------------------------------------------------------------------------
__global__ __launch_bounds__(256) void attn_mma_kernel(float* __restrict__ out)
{
    __shared__ __align__(16) __half sm[4][64 * 64];

    const int b    = blockIdx.y;
    const int qt   = (int)gridDim.x - 1 - (int)blockIdx.x;   // heavy blocks first
    const int tid  = threadIdx.x;
    const int lane = tid & 31;
    const int w    = tid >> 5;
    const int g    = lane >> 2;     // row group 0..7
    const int tig  = lane & 3;      // col pair selector
    const int lr   = lane & 7;
    const int mat  = lane >> 3;     // ldmatrix sub-matrix id 0..3
    const float NEG = __int_as_float(0xff800000);

    __half* sQ  = &sm[0][0];        // 128x64 staging view (spans sm[0..1])
    __half* sKh = &sm[0][0];
    __half* sKl = &sm[1][0];
    __half* sVh = &sm[2][0];
    __half* sVl = &sm[3][0];

    const int row0_g = qt * 128 + w * 16 + g;   // global q row of c0/c1
    const int row1_g = row0_g + 8;              // global q row of c2/c3

    // ---- Stage Q (hi then lo through same buffer), preload A fragments ----
    uint32_t aQh[4][4], aQl[4][4];
    {
        const int qrow = w * 16 + lr + ((mat & 1) << 3);
        const __half* gqh = g_qh + ((size_t)b * SEQ + qt * 128) * HDIM;
        const __half* gql = g_ql + ((size_t)b * SEQ + qt * 128) * HDIM;

        for (int i = tid; i < 128 * 8; i += 256) {
            int r = i >> 3, cb = i & 7;
            *(uint4*)(sQ + r * 64 + ((cb ^ (r & 7)) << 3)) =
                *(const uint4*)(gqh + r * 64 + (cb << 3));
        }
        __syncthreads();
        #pragma unroll
        for (int kc = 0; kc < 4; kc++) {
            int cb = kc * 2 + (mat >> 1);
            ldsm_x4(aQh[kc], smem_u32(sQ + qrow * 64 + ((cb ^ (qrow & 7)) << 3)));
        }
        __syncthreads();
        for (int i = tid; i < 128 * 8; i += 256) {
            int r = i >> 3, cb = i & 7;
            *(uint4*)(sQ + r * 64 + ((cb ^ (r & 7)) << 3)) =
                *(const uint4*)(gql + r * 64 + (cb << 3));
        }
        __syncthreads();
        #pragma unroll
        for (int kc = 0; kc < 4; kc++) {
            int cb = kc * 2 + (mat >> 1);
            ldsm_x4(aQl[kc], smem_u32(sQ + qrow * 64 + ((cb ^ (qrow & 7)) << 3)));
        }
    }

    float Oacc[8][4];
    #pragma unroll
    for (int nh = 0; nh < 8; nh++)
        #pragma unroll
        for (int c = 0; c < 4; c++) Oacc[nh][c] = 0.f;
    float m0 = NEG, m1 = NEG, l0 = 0.f, l1 = 0.f;

    const int nkt = 2 * qt + 2;

    for (int kt = 0; kt < nkt; kt++) {
        const int j0 = kt * 64;
        const __half* pkh = g_kh + ((size_t)b * SEQ + j0) * HDIM;
        const __half* pkl = g_kl + ((size_t)b * SEQ + j0) * HDIM;
        const __half* pvh = g_vh + ((size_t)b * SEQ + j0) * HDIM;
        const __half* pvl = g_vl + ((size_t)b * SEQ + j0) * HDIM;

        __syncthreads();             // previous tile fully consumed
        #pragma unroll
        for (int rep = 0; rep < 2; rep++) {
            int i  = tid + rep * 256;          // 0..511
            int r  = i >> 3, cb = i & 7;
            int so = r * 64 + ((cb ^ (r & 7)) << 3);
            int go = r * 64 + (cb << 3);
            *(uint4*)(sKh + so) = *(const uint4*)(pkh + go);
            *(uint4*)(sKl + so) = *(const uint4*)(pkl + go);
            *(uint4*)(sVh + so) = *(const uint4*)(pvh + go);
            *(uint4*)(sVl + so) = *(const uint4*)(pvl + go);
        }
        __syncthreads();

        // ---- S = Q.K^T (split precision, fp32 accum) ----
        float sacc[8][4];
        #pragma unroll
        for (int nt = 0; nt < 8; nt++)
            #pragma unroll
            for (int c = 0; c < 4; c++) sacc[nt][c] = 0.f;

        #pragma unroll
        for (int kp = 0; kp < 2; kp++) {
            #pragma unroll
            for (int nt = 0; nt < 8; nt++) {
                int krow = nt * 8 + lr;
                int cb   = kp * 4 + mat;
                int soff = krow * 64 + ((cb ^ (krow & 7)) << 3);
                uint32_t bh[4], bl[4];
                ldsm_x4(bh, smem_u32(sKh + soff));
                ldsm_x4(bl, smem_u32(sKl + soff));
                mma_f16(sacc[nt], aQh[2 * kp],     bh[0], bh[1]);
                mma_f16(sacc[nt], aQh[2 * kp],     bl[0], bl[1]);
                mma_f16(sacc[nt], aQl[2 * kp],     bh[0], bh[1]);
                mma_f16(sacc[nt], aQh[2 * kp + 1], bh[2], bh[3]);
                mma_f16(sacc[nt], aQh[2 * kp + 1], bl[2], bl[3]);
                mma_f16(sacc[nt], aQl[2 * kp + 1], bh[2], bh[3]);
            }
        }

        // ---- causal mask + online softmax (2 rows per thread) ----
        float mt0 = NEG, mt1 = NEG;
        #pragma unroll
        for (int nt = 0; nt < 8; nt++) {
            int j = j0 + nt * 8 + tig * 2;
            sacc[nt][0] = (j     <= row0_g) ? sacc[nt][0] : NEG;
            sacc[nt][1] = (j + 1 <= row0_g) ? sacc[nt][1] : NEG;
            sacc[nt][2] = (j     <= row1_g) ? sacc[nt][2] : NEG;
            sacc[nt][3] = (j + 1 <= row1_g) ? sacc[nt][3] : NEG;
            mt0 = fmaxf(mt0, fmaxf(sacc[nt][0], sacc[nt][1]));
            mt1 = fmaxf(mt1, fmaxf(sacc[nt][2], sacc[nt][3]));
        }
        mt0 = fmaxf(mt0, __shfl_xor_sync(0xffffffffu, mt0, 1));
        mt0 = fmaxf(mt0, __shfl_xor_sync(0xffffffffu, mt0, 2));
        mt1 = fmaxf(mt1, __shfl_xor_sync(0xffffffffu, mt1, 1));
        mt1 = fmaxf(mt1, __shfl_xor_sync(0xffffffffu, mt1, 2));

        const float mn0 = fmaxf(m0, mt0);
        const float mn1 = fmaxf(m1, mt1);
        const float cr0 = __expf(m0 - mn0);
        const float cr1 = __expf(m1 - mn1);
        m0 = mn0; m1 = mn1;

        float ls0 = 0.f, ls1 = 0.f;
        #pragma unroll
        for (int nt = 0; nt < 8; nt++) {
            sacc[nt][0] = __expf(sacc[nt][0] - mn0);
            sacc[nt][1] = __expf(sacc[nt][1] - mn0);
            sacc[nt][2] = __expf(sacc[nt][2] - mn1);
            sacc[nt][3] = __expf(sacc[nt][3] - mn1);
            ls0 += sacc[nt][0] + sacc[nt][1];
            ls1 += sacc[nt][2] + sacc[nt][3];
        }
        l0 = l0 * cr0 + ls0;
        l1 = l1 * cr1 + ls1;

        #pragma unroll
        for (int nh = 0; nh < 8; nh++) {
            Oacc[nh][0] *= cr0; Oacc[nh][1] *= cr0;
            Oacc[nh][2] *= cr1; Oacc[nh][3] *= cr1;
        }

        // ---- O += P.V (P from S accumulators via fragment identity) ----
        #pragma unroll
        for (int kc = 0; kc < 4; kc++) {
            uint32_t aPh[4], aPl[4];
            split_pair(sacc[2 * kc][0],     sacc[2 * kc][1],     aPh[0], aPl[0]);
            split_pair(sacc[2 * kc][2],     sacc[2 * kc][3],     aPh[1], aPl[1]);
            split_pair(sacc[2 * kc + 1][0], sacc[2 * kc + 1][1], aPh[2], aPl[2]);
            split_pair(sacc[2 * kc + 1][2], sacc[2 * kc + 1][3], aPh[3], aPl[3]);

            #pragma unroll
            for (int np = 0; np < 4; np++) {
                int vrow = kc * 16 + lr + ((mat & 1) << 3);
                int cb   = np * 2 + (mat >> 1);
                int soff = vrow * 64 + ((cb ^ (vrow & 7)) << 3);
                uint32_t bh[4], bl[4];
                ldsm_x4_t(bh, smem_u32(sVh + soff));
                ldsm_x4_t(bl, smem_u32(sVl + soff));
                mma_f16(Oacc[2 * np],     aPh, bh[0], bh[1]);
                mma_f16(Oacc[2 * np],     aPh, bl[0], bl[1]);
                mma_f16(Oacc[2 * np],     aPl, bh[0], bh[1]);
                mma_f16(Oacc[2 * np + 1], aPh, bh[2], bh[3]);
                mma_f16(Oacc[2 * np + 1], aPh, bl[2], bl[3]);
                mma_f16(Oacc[2 * np + 1], aPl, bh[2], bh[3]);
            }
        }
    }

    // ---- epilogue: finish row sums, normalize, store ----
    l0 += __shfl_xor_sync(0xffffffffu, l0, 1);
    l0 += __shfl_xor_sync(0xffffffffu, l0, 2);
    l1 += __shfl_xor_sync(0xffffffffu, l1, 1);
    l1 += __shfl_xor_sync(0xffffffffu, l1, 2);
    const float inv0 = 1.f / l0;
    const float inv1 = 1.f / l1;

    float* po = out + (size_t)b * SEQ * HDIM;
    #pragma unroll
    for (int nh = 0; nh < 8; nh++) {
        int c = nh * 8 + tig * 2;
        *(float2*)(po + (size_t)row0_g * HDIM + c) =
            make_float2(Oacc[nh][0] * inv0, Oacc[nh][1] * inv0);
        *(float2*)(po + (size_t)row1_g * HDIM + c) =
            make_float2(Oacc[nh][2] * inv1, Oacc[nh][3] * inv1);
    }
}

// ---------------------------------------------------------------------------
extern "C" void kernel_launch(void* const* d_in, const int* in_sizes, int n_in,
                              void* d_out, int out_size)
{
    const float* x  = (const float*)d_in[0];
    const float* Wk = (const float*)d_in[1];
    const float* Wq = (const float*)d_in[2];
    const float* Wv = (const float*)d_in[3];
    float* out = (float*)d_out;

    (void)in_sizes; (void)n_in; (void)out_size;

    qkv_proj_kernel<<<BT / 64, 256>>>(x, Wk, Wq, Wv);
    attn_mma_kernel<<<dim3(SEQ / 128, BATCH), 256>>>(out);
}

// round 9
// speedup vs baseline: 5.7136x; 1.4297x over previous
#include <cuda_runtime.h>
#include <cuda_fp16.h>
#include <math.h>
#include <stdint.h>

// Problem constants
#define BATCH 32
#define SEQ   2048
#define CDIM  384
#define HDIM  64
#define BT    (BATCH * SEQ)

// Projected q,k,v stored as fp16 hi/lo split pairs (value = hi + lo, ~22-bit precision)
__device__ __half g_qh[BT * HDIM];
__device__ __half g_ql[BT * HDIM];
__device__ __half g_kh[BT * HDIM];
__device__ __half g_kl[BT * HDIM];
__device__ __half g_vh[BT * HDIM];
__device__ __half g_vl[BT * HDIM];

// ===========================================================================
// Warp-MMA helpers (sm_80+ baseline PTX: no 'a'-suffix features needed)
// ===========================================================================
__device__ __forceinline__ uint32_t smem_u32(const void* p) {
    uint32_t a;
    asm("{ .reg .u64 t; cvta.to.shared.u64 t, %1; cvt.u32.u64 %0, t; }"
        : "=r"(a) : "l"(p));
    return a;
}

__device__ __forceinline__ void ldsm_x4(uint32_t* r, uint32_t a) {
    asm volatile("ldmatrix.sync.aligned.m8n8.x4.shared.b16 {%0,%1,%2,%3}, [%4];"
                 : "=r"(r[0]), "=r"(r[1]), "=r"(r[2]), "=r"(r[3]) : "r"(a));
}
__device__ __forceinline__ void ldsm_x4_t(uint32_t* r, uint32_t a) {
    asm volatile("ldmatrix.sync.aligned.m8n8.x4.trans.shared.b16 {%0,%1,%2,%3}, [%4];"
                 : "=r"(r[0]), "=r"(r[1]), "=r"(r[2]), "=r"(r[3]) : "r"(a));
}

__device__ __forceinline__ void mma_f16(float* c, const uint32_t* a,
                                        uint32_t b0, uint32_t b1) {
    asm volatile(
        "mma.sync.aligned.m16n8k16.row.col.f32.f16.f16.f32 "
        "{%0,%1,%2,%3}, {%4,%5,%6,%7}, {%8,%9}, {%0,%1,%2,%3};"
        : "+f"(c[0]), "+f"(c[1]), "+f"(c[2]), "+f"(c[3])
        : "r"(a[0]), "r"(a[1]), "r"(a[2]), "r"(a[3]), "r"(b0), "r"(b1));
}

__device__ __forceinline__ void cp_async16(uint32_t dst, const void* src) {
    asm volatile("cp.async.cg.shared.global [%0], [%1], 16;" :: "r"(dst), "l"(src));
}
#define CP_COMMIT() asm volatile("cp.async.commit_group;" ::: "memory")
#define CP_WAIT1()  asm volatile("cp.async.wait_group 1;" ::: "memory")

__device__ __forceinline__ uint32_t pack_h2(__half x, __half y) {
    __half2 t = __halves2half2(x, y);
    return *(uint32_t*)&t;
}

// Split a float pair into packed fp16 hi and lo words.
__device__ __forceinline__ void split_pair(float x, float y,
                                           uint32_t& hi, uint32_t& lo) {
    __half hx = __float2half(x);
    __half hy = __float2half(y);
    __half lx = __float2half(x - __half2float(hx));
    __half ly = __float2half(y - __half2float(hy));
    hi = pack_h2(hx, hy);
    lo = pack_h2(lx, ly);
}

// ---------------------------------------------------------------------------
// Kernel 1: fused QKV projection via split-fp16 HMMA.
// Block: 256 thr / 8 warps, output tile 128 rows x 192 cols (3 mats x 64).
// Warp tile 32x96 (wm = w>>1, wn = w&1). K chunks of 64, X prefetched into
// registers one chunk ahead; W staged per chunk (L2-hot after wave 1).
// Epilogue emits fp16 hi/lo split arrays; H^{-1/2} folded into q.
// ---------------------------------------------------------------------------
__global__ __launch_bounds__(256) void qkv_mma_kernel(
    const float* __restrict__ x,
    const float* __restrict__ Wk,
    const float* __restrict__ Wq,
    const float* __restrict__ Wv)
{
    extern __shared__ __half smp[];
    __half* sXh = smp;                 // 128 x 64 halves (8192)
    __half* sXl = smp + 8192;
    __half* sWh = smp + 16384;         // 64 x 192 halves (12288)
    __half* sWl = smp + 28672;

    const int m0   = blockIdx.x * 128;
    const int tid  = threadIdx.x;
    const int lane = tid & 31;
    const int w    = tid >> 5;
    const int wm   = w >> 1;           // 0..3
    const int wn   = w & 1;            // 0..1
    const int wrow0 = wm * 32;
    const int lr   = lane & 7;
    const int mat  = lane >> 3;
    const int g    = lane >> 2;
    const int tig  = lane & 3;

    const float* Wmat[3] = {Wq, Wk, Wv};

    float C[2][12][4];
    #pragma unroll
    for (int mt = 0; mt < 2; mt++)
        #pragma unroll
        for (int nf = 0; nf < 12; nf++)
            #pragma unroll
            for (int c = 0; c < 4; c++) C[mt][nf][c] = 0.f;

    // prefetch X chunk 0 into registers
    float4 px[8];
    #pragma unroll
    for (int rep = 0; rep < 8; rep++) {
        int id = tid + rep * 256;
        int r  = id >> 4;
        int c4 = (id & 15) * 4;
        px[rep] = *(const float4*)(x + (size_t)(m0 + r) * CDIM + c4);
    }

    for (int c = 0; c < 6; c++) {
        const int k0 = c * 64;

        // ---- STS X (split hi/lo, swizzled) from prefetched regs ----
        #pragma unroll
        for (int rep = 0; rep < 8; rep++) {
            int id = tid + rep * 256;
            int r  = id >> 4;
            int c4 = (id & 15) * 4;
            uint32_t h01, l01, h23, l23;
            split_pair(px[rep].x, px[rep].y, h01, l01);
            split_pair(px[rep].z, px[rep].w, h23, l23);
            int off = r * 64 + (((c4 >> 3) ^ (r & 7)) << 3) + (c4 & 7);
            *(uint2*)(sXh + off) = make_uint2(h01, h23);
            *(uint2*)(sXl + off) = make_uint2(l01, l23);
        }
        // ---- LDG + STS W (split hi/lo, swizzled) ----
        #pragma unroll
        for (int mm = 0; mm < 3; mm++) {
            #pragma unroll
            for (int rep = 0; rep < 4; rep++) {
                int id = tid + rep * 256;
                int r  = id >> 4;
                int c4 = (id & 15) * 4;
                float4 v = *(const float4*)(Wmat[mm] + (size_t)(k0 + r) * HDIM + c4);
                uint32_t h01, l01, h23, l23;
                split_pair(v.x, v.y, h01, l01);
                split_pair(v.z, v.w, h23, l23);
                int colh = mm * 64 + c4;
                int off  = r * 192 + ((((colh >> 3)) ^ (r & 7)) << 3) + (colh & 7);
                *(uint2*)(sWh + off) = make_uint2(h01, h23);
                *(uint2*)(sWl + off) = make_uint2(l01, l23);
            }
        }
        __syncthreads();

        // ---- prefetch next X chunk (LDG overlapped with MMA below) ----
        if (c < 5) {
            #pragma unroll
            for (int rep = 0; rep < 8; rep++) {
                int id = tid + rep * 256;
                int r  = id >> 4;
                int c4 = (id & 15) * 4;
                px[rep] = *(const float4*)(x + (size_t)(m0 + r) * CDIM + k0 + 64 + c4);
            }
        }

        // ---- MMA: 4 k-steps of 16, split-precision 3 passes ----
        #pragma unroll
        for (int ks = 0; ks < 4; ks++) {
            uint32_t aXh[2][4], aXl[2][4];
            #pragma unroll
            for (int mt = 0; mt < 2; mt++) {
                int arow = wrow0 + mt * 16 + lr + ((mat & 1) << 3);
                int kb   = ks * 2 + (mat >> 1);
                int aoff = arow * 64 + ((kb ^ (arow & 7)) << 3);
                ldsm_x4(aXh[mt], smem_u32(sXh + aoff));
                ldsm_x4(aXl[mt], smem_u32(sXl + aoff));
            }
            #pragma unroll
            for (int nb = 0; nb < 6; nb++) {
                int brow = ks * 16 + lr + ((mat & 1) << 3);
                int cbg  = wn * 12 + nb * 2 + (mat >> 1);
                int boff = brow * 192 + ((cbg ^ (brow & 7)) << 3);
                uint32_t bh[4], bl[4];
                ldsm_x4_t(bh, smem_u32(sWh + boff));
                ldsm_x4_t(bl, smem_u32(sWl + boff));
                #pragma unroll
                for (int mt = 0; mt < 2; mt++) {
                    mma_f16(C[mt][2 * nb],     aXh[mt], bh[0], bh[1]);
                    mma_f16(C[mt][2 * nb],     aXh[mt], bl[0], bl[1]);
                    mma_f16(C[mt][2 * nb],     aXl[mt], bh[0], bh[1]);
                    mma_f16(C[mt][2 * nb + 1], aXh[mt], bh[2], bh[3]);
                    mma_f16(C[mt][2 * nb + 1], aXh[mt], bl[2], bl[3]);
                    mma_f16(C[mt][2 * nb + 1], aXl[mt], bh[2], bh[3]);
                }
            }
        }
        __syncthreads();
    }

    // ---- epilogue: scale q, split to hi/lo fp16 arrays ----
    #pragma unroll
    for (int mt = 0; mt < 2; mt++) {
        #pragma unroll
        for (int nf = 0; nf < 12; nf++) {
            int col = wn * 96 + nf * 8 + tig * 2;
            int mm  = col >> 6;
            int cin = col & 63;
            __half* ohp = (mm == 0) ? g_qh : ((mm == 1) ? g_kh : g_vh);
            __half* olp = (mm == 0) ? g_ql : ((mm == 1) ? g_kl : g_vl);
            float s = (mm == 0) ? 0.125f : 1.f;
            size_t r0 = (size_t)(m0 + wrow0 + mt * 16 + g);
            uint32_t h01, l01, h23, l23;
            split_pair(C[mt][nf][0] * s, C[mt][nf][1] * s, h01, l01);
            split_pair(C[mt][nf][2] * s, C[mt][nf][3] * s, h23, l23);
            *(uint32_t*)(ohp + r0 * 64 + cin)       = h01;
            *(uint32_t*)(olp + r0 * 64 + cin)       = l01;
            *(uint32_t*)(ohp + (r0 + 8) * 64 + cin) = h23;
            *(uint32_t*)(olp + (r0 + 8) * 64 + cin) = l23;
        }
    }
}

// ---------------------------------------------------------------------------
// Kernel 2: warp-MMA flash attention, cp.async double-buffered K/V tiles.
// Block: 256 threads / 8 warps, 128 q-rows (16 per warp), 64-key tiles.
// Smem: 2 buffers x {Kh,Kl,Vh,Vl} 64x64 half tiles (64KB dynamic).
// ---------------------------------------------------------------------------
__global__ __launch_bounds__(256) void attn_mma_kernel(float* __restrict__ out)
{
    extern __shared__ __half smp[];
    const uint32_t sbase = smem_u32(smp);

    const int b    = blockIdx.y;
    const int qt   = (int)gridDim.x - 1 - (int)blockIdx.x;   // heavy blocks first
    const int tid  = threadIdx.x;
    const int lane = tid & 31;
    const int w    = tid >> 5;
    const int g    = lane >> 2;
    const int tig  = lane & 3;
    const int lr   = lane & 7;
    const int mat  = lane >> 3;
    const float NEG = __int_as_float(0xff800000);

    const int row0_g = qt * 128 + w * 16 + g;
    const int row1_g = row0_g + 8;

    // ---- Stage Q (hi then lo through buffer 0), preload A fragments ----
    uint32_t aQh[4][4], aQl[4][4];
    {
        __half* sQ = smp;
        const int qrow = w * 16 + lr + ((mat & 1) << 3);
        const __half* gqh = g_qh + ((size_t)b * SEQ + qt * 128) * HDIM;
        const __half* gql = g_ql + ((size_t)b * SEQ + qt * 128) * HDIM;

        for (int i = tid; i < 128 * 8; i += 256) {
            int r = i >> 3, cb = i & 7;
            *(uint4*)(sQ + r * 64 + ((cb ^ (r & 7)) << 3)) =
                *(const uint4*)(gqh + r * 64 + (cb << 3));
        }
        __syncthreads();
        #pragma unroll
        for (int kc = 0; kc < 4; kc++) {
            int cb = kc * 2 + (mat >> 1);
            ldsm_x4(aQh[kc], smem_u32(sQ + qrow * 64 + ((cb ^ (qrow & 7)) << 3)));
        }
        __syncthreads();
        for (int i = tid; i < 128 * 8; i += 256) {
            int r = i >> 3, cb = i & 7;
            *(uint4*)(sQ + r * 64 + ((cb ^ (r & 7)) << 3)) =
                *(const uint4*)(gql + r * 64 + (cb << 3));
        }
        __syncthreads();
        #pragma unroll
        for (int kc = 0; kc < 4; kc++) {
            int cb = kc * 2 + (mat >> 1);
            ldsm_x4(aQl[kc], smem_u32(sQ + qrow * 64 + ((cb ^ (qrow & 7)) << 3)));
        }
        __syncthreads();    // all Q fragments read before cp.async overwrites buf0
    }

    float Oacc[8][4];
    #pragma unroll
    for (int nh = 0; nh < 8; nh++)
        #pragma unroll
        for (int c = 0; c < 4; c++) Oacc[nh][c] = 0.f;
    float m0 = NEG, m1 = NEG, l0 = 0.f, l1 = 0.f;

    const int nkt = 2 * qt + 2;
    const size_t bbase = (size_t)b * SEQ * HDIM;

    // ---- prologue: async-load tile 0 into buffer 0 ----
    {
        const __half* pkh = g_kh + bbase;
        const __half* pkl = g_kl + bbase;
        const __half* pvh = g_vh + bbase;
        const __half* pvl = g_vl + bbase;
        #pragma unroll
        for (int rep = 0; rep < 2; rep++) {
            int i  = tid + rep * 256;
            int r  = i >> 3, cb = i & 7;
            uint32_t so = (uint32_t)(r * 64 + ((cb ^ (r & 7)) << 3)) * 2;
            int go = r * 64 + cb * 8;
            cp_async16(sbase + 0     + so, pkh + go);
            cp_async16(sbase + 8192  + so, pkl + go);
            cp_async16(sbase + 16384 + so, pvh + go);
            cp_async16(sbase + 24576 + so, pvl + go);
        }
        CP_COMMIT();
    }

    for (int kt = 0; kt < nkt; kt++) {
        const int cur = kt & 1;
        const int nxt = cur ^ 1;

        // ---- prefetch tile kt+1 into other buffer ----
        if (kt + 1 < nkt) {
            const size_t tb = bbase + (size_t)(kt + 1) * 64 * HDIM;
            const __half* pkh = g_kh + tb;
            const __half* pkl = g_kl + tb;
            const __half* pvh = g_vh + tb;
            const __half* pvl = g_vl + tb;
            const uint32_t db = sbase + (uint32_t)nxt * 32768u;
            #pragma unroll
            for (int rep = 0; rep < 2; rep++) {
                int i  = tid + rep * 256;
                int r  = i >> 3, cb = i & 7;
                uint32_t so = (uint32_t)(r * 64 + ((cb ^ (r & 7)) << 3)) * 2;
                int go = r * 64 + cb * 8;
                cp_async16(db + 0     + so, pkh + go);
                cp_async16(db + 8192  + so, pkl + go);
                cp_async16(db + 16384 + so, pvh + go);
                cp_async16(db + 24576 + so, pvl + go);
            }
        }
        CP_COMMIT();
        CP_WAIT1();            // tile kt's group complete
        __syncthreads();

        const __half* sKh = smp + cur * 16384;
        const __half* sKl = sKh + 4096;
        const __half* sVh = sKh + 8192;
        const __half* sVl = sKh + 12288;
        const int j0 = kt * 64;

        // ---- S = Q.K^T (split precision, fp32 accum) ----
        float sacc[8][4];
        #pragma unroll
        for (int nt = 0; nt < 8; nt++)
            #pragma unroll
            for (int c = 0; c < 4; c++) sacc[nt][c] = 0.f;

        #pragma unroll
        for (int kp = 0; kp < 2; kp++) {
            #pragma unroll
            for (int nt = 0; nt < 8; nt++) {
                int krow = nt * 8 + lr;
                int cb   = kp * 4 + mat;
                int soff = krow * 64 + ((cb ^ (krow & 7)) << 3);
                uint32_t bh[4], bl[4];
                ldsm_x4(bh, smem_u32(sKh + soff));
                ldsm_x4(bl, smem_u32(sKl + soff));
                mma_f16(sacc[nt], aQh[2 * kp],     bh[0], bh[1]);
                mma_f16(sacc[nt], aQh[2 * kp],     bl[0], bl[1]);
                mma_f16(sacc[nt], aQl[2 * kp],     bh[0], bh[1]);
                mma_f16(sacc[nt], aQh[2 * kp + 1], bh[2], bh[3]);
                mma_f16(sacc[nt], aQh[2 * kp + 1], bl[2], bl[3]);
                mma_f16(sacc[nt], aQl[2 * kp + 1], bh[2], bh[3]);
            }
        }

        // ---- causal mask + online softmax (2 rows per thread) ----
        float mt0 = NEG, mt1 = NEG;
        #pragma unroll
        for (int nt = 0; nt < 8; nt++) {
            int j = j0 + nt * 8 + tig * 2;
            sacc[nt][0] = (j     <= row0_g) ? sacc[nt][0] : NEG;
            sacc[nt][1] = (j + 1 <= row0_g) ? sacc[nt][1] : NEG;
            sacc[nt][2] = (j     <= row1_g) ? sacc[nt][2] : NEG;
            sacc[nt][3] = (j + 1 <= row1_g) ? sacc[nt][3] : NEG;
            mt0 = fmaxf(mt0, fmaxf(sacc[nt][0], sacc[nt][1]));
            mt1 = fmaxf(mt1, fmaxf(sacc[nt][2], sacc[nt][3]));
        }
        mt0 = fmaxf(mt0, __shfl_xor_sync(0xffffffffu, mt0, 1));
        mt0 = fmaxf(mt0, __shfl_xor_sync(0xffffffffu, mt0, 2));
        mt1 = fmaxf(mt1, __shfl_xor_sync(0xffffffffu, mt1, 1));
        mt1 = fmaxf(mt1, __shfl_xor_sync(0xffffffffu, mt1, 2));

        const float mn0 = fmaxf(m0, mt0);
        const float mn1 = fmaxf(m1, mt1);
        const float cr0 = __expf(m0 - mn0);
        const float cr1 = __expf(m1 - mn1);
        m0 = mn0; m1 = mn1;

        float ls0 = 0.f, ls1 = 0.f;
        #pragma unroll
        for (int nt = 0; nt < 8; nt++) {
            sacc[nt][0] = __expf(sacc[nt][0] - mn0);
            sacc[nt][1] = __expf(sacc[nt][1] - mn0);
            sacc[nt][2] = __expf(sacc[nt][2] - mn1);
            sacc[nt][3] = __expf(sacc[nt][3] - mn1);
            ls0 += sacc[nt][0] + sacc[nt][1];
            ls1 += sacc[nt][2] + sacc[nt][3];
        }
        l0 = l0 * cr0 + ls0;
        l1 = l1 * cr1 + ls1;

        #pragma unroll
        for (int nh = 0; nh < 8; nh++) {
            Oacc[nh][0] *= cr0; Oacc[nh][1] *= cr0;
            Oacc[nh][2] *= cr1; Oacc[nh][3] *= cr1;
        }

        // ---- O += P.V (P from S accumulators via fragment identity) ----
        #pragma unroll
        for (int kc = 0; kc < 4; kc++) {
            uint32_t aPh[4], aPl[4];
            split_pair(sacc[2 * kc][0],     sacc[2 * kc][1],     aPh[0], aPl[0]);
            split_pair(sacc[2 * kc][2],     sacc[2 * kc][3],     aPh[1], aPl[1]);
            split_pair(sacc[2 * kc + 1][0], sacc[2 * kc + 1][1], aPh[2], aPl[2]);
            split_pair(sacc[2 * kc + 1][2], sacc[2 * kc + 1][3], aPh[3], aPl[3]);

            #pragma unroll
            for (int np = 0; np < 4; np++) {
                int vrow = kc * 16 + lr + ((mat & 1) << 3);
                int cb   = np * 2 + (mat >> 1);
                int soff = vrow * 64 + ((cb ^ (vrow & 7)) << 3);
                uint32_t bh[4], bl[4];
                ldsm_x4_t(bh, smem_u32(sVh + soff));
                ldsm_x4_t(bl, smem_u32(sVl + soff));
                mma_f16(Oacc[2 * np],     aPh, bh[0], bh[1]);
                mma_f16(Oacc[2 * np],     aPh, bl[0], bl[1]);
                mma_f16(Oacc[2 * np],     aPl, bh[0], bh[1]);
                mma_f16(Oacc[2 * np + 1], aPh, bh[2], bh[3]);
                mma_f16(Oacc[2 * np + 1], aPh, bl[2], bl[3]);
                mma_f16(Oacc[2 * np + 1], aPl, bh[2], bh[3]);
            }
        }
        __syncthreads();     // buffer cur fully consumed before it is refilled
    }

    // ---- epilogue: finish row sums, normalize, store ----
    l0 += __shfl_xor_sync(0xffffffffu, l0, 1);
    l0 += __shfl_xor_sync(0xffffffffu, l0, 2);
    l1 += __shfl_xor_sync(0xffffffffu, l1, 1);
    l1 += __shfl_xor_sync(0xffffffffu, l1, 2);
    const float inv0 = 1.f / l0;
    const float inv1 = 1.f / l1;

    float* po = out + (size_t)b * SEQ * HDIM;
    #pragma unroll
    for (int nh = 0; nh < 8; nh++) {
        int c = nh * 8 + tig * 2;
        *(float2*)(po + (size_t)row0_g * HDIM + c) =
            make_float2(Oacc[nh][0] * inv0, Oacc[nh][1] * inv0);
        *(float2*)(po + (size_t)row1_g * HDIM + c) =
            make_float2(Oacc[nh][2] * inv1, Oacc[nh][3] * inv1);
    }
}

// ---------------------------------------------------------------------------
extern "C" void kernel_launch(void* const* d_in, const int* in_sizes, int n_in,
                              void* d_out, int out_size)
{
    const float* x  = (const float*)d_in[0];
    const float* Wk = (const float*)d_in[1];
    const float* Wq = (const float*)d_in[2];
    const float* Wv = (const float*)d_in[3];
    float* out = (float*)d_out;

    (void)in_sizes; (void)n_in; (void)out_size;

    cudaFuncSetAttribute(qkv_mma_kernel,
                         cudaFuncAttributeMaxDynamicSharedMemorySize, 81920);
    cudaFuncSetAttribute(attn_mma_kernel,
                         cudaFuncAttributeMaxDynamicSharedMemorySize, 65536);

    qkv_mma_kernel<<<BT / 128, 256, 81920>>>(x, Wk, Wq, Wv);
    attn_mma_kernel<<<dim3(SEQ / 128, BATCH), 256, 65536>>>(out);
}

// round 11
// speedup vs baseline: 7.0184x; 1.2284x over previous
#include <cuda_runtime.h>
#include <cuda_fp16.h>
#include <math.h>
#include <stdint.h>

// Problem constants
#define BATCH 32
#define SEQ   2048
#define CDIM  384
#define HDIM  64
#define BT    (BATCH * SEQ)

// Projected q,k,v. q,v stored hi-only; k stored as fp16 hi/lo split.
__device__ __half g_qh[BT * HDIM];
__device__ __half g_kh[BT * HDIM];
__device__ __half g_kl[BT * HDIM];
__device__ __half g_vh[BT * HDIM];

// ===========================================================================
// Warp-MMA helpers (sm_80+ baseline PTX)
// ===========================================================================
__device__ __forceinline__ uint32_t smem_u32(const void* p) {
    uint32_t a;
    asm("{ .reg .u64 t; cvta.to.shared.u64 t, %1; cvt.u32.u64 %0, t; }"
        : "=r"(a) : "l"(p));
    return a;
}

__device__ __forceinline__ void ldsm_x4(uint32_t* r, uint32_t a) {
    asm volatile("ldmatrix.sync.aligned.m8n8.x4.shared.b16 {%0,%1,%2,%3}, [%4];"
                 : "=r"(r[0]), "=r"(r[1]), "=r"(r[2]), "=r"(r[3]) : "r"(a));
}
__device__ __forceinline__ void ldsm_x4_t(uint32_t* r, uint32_t a) {
    asm volatile("ldmatrix.sync.aligned.m8n8.x4.trans.shared.b16 {%0,%1,%2,%3}, [%4];"
                 : "=r"(r[0]), "=r"(r[1]), "=r"(r[2]), "=r"(r[3]) : "r"(a));
}

__device__ __forceinline__ void mma_f16(float* c, const uint32_t* a,
                                        uint32_t b0, uint32_t b1) {
    asm volatile(
        "mma.sync.aligned.m16n8k16.row.col.f32.f16.f16.f32 "
        "{%0,%1,%2,%3}, {%4,%5,%6,%7}, {%8,%9}, {%0,%1,%2,%3};"
        : "+f"(c[0]), "+f"(c[1]), "+f"(c[2]), "+f"(c[3])
        : "r"(a[0]), "r"(a[1]), "r"(a[2]), "r"(a[3]), "r"(b0), "r"(b1));
}

__device__ __forceinline__ void cp_async16(uint32_t dst, const void* src) {
    asm volatile("cp.async.cg.shared.global [%0], [%1], 16;" :: "r"(dst), "l"(src));
}
#define CP_COMMIT() asm volatile("cp.async.commit_group;" ::: "memory")
#define CP_WAIT1()  asm volatile("cp.async.wait_group 1;" ::: "memory")

__device__ __forceinline__ uint32_t pack_h2(__half x, __half y) {
    __half2 t = __halves2half2(x, y);
    return *(uint32_t*)&t;
}

// Split a float pair into packed fp16 hi and lo words.
__device__ __forceinline__ void split_pair(float x, float y,
                                           uint32_t& hi, uint32_t& lo) {
    __half hx = __float2half(x);
    __half hy = __float2half(y);
    __half lx = __float2half(x - __half2float(hx));
    __half ly = __float2half(y - __half2float(hy));
    hi = pack_h2(hx, hy);
    lo = pack_h2(lx, ly);
}

// ---------------------------------------------------------------------------
// Kernel 1: fused QKV projection via split-fp16 HMMA (3-pass, full precision).
// Block: 256 thr / 8 warps, output tile 128 rows x 192 cols (3 mats x 64).
// Epilogue: q scaled by H^{-1/2}, stored hi-only; k stored hi/lo; v hi-only.
// ---------------------------------------------------------------------------
__global__ __launch_bounds__(256) void qkv_mma_kernel(
    const float* __restrict__ x,
    const float* __restrict__ Wk,
    const float* __restrict__ Wq,
    const float* __restrict__ Wv)
{
    extern __shared__ __half smp[];
    __half* sXh = smp;                 // 128 x 64 halves (8192)
    __half* sXl = smp + 8192;
    __half* sWh = smp + 16384;         // 64 x 192 halves (12288)
    __half* sWl = smp + 28672;

    const int m0   = blockIdx.x * 128;
    const int tid  = threadIdx.x;
    const int lane = tid & 31;
    const int w    = tid >> 5;
    const int wm   = w >> 1;           // 0..3
    const int wn   = w & 1;            // 0..1
    const int wrow0 = wm * 32;
    const int lr   = lane & 7;
    const int mat  = lane >> 3;
    const int g    = lane >> 2;
    const int tig  = lane & 3;

    const float* Wmat[3] = {Wq, Wk, Wv};

    float C[2][12][4];
    #pragma unroll
    for (int mt = 0; mt < 2; mt++)
        #pragma unroll
        for (int nf = 0; nf < 12; nf++)
            #pragma unroll
            for (int c = 0; c < 4; c++) C[mt][nf][c] = 0.f;

    // prefetch X chunk 0 into registers
    float4 px[8];
    #pragma unroll
    for (int rep = 0; rep < 8; rep++) {
        int id = tid + rep * 256;
        int r  = id >> 4;
        int c4 = (id & 15) * 4;
        px[rep] = *(const float4*)(x + (size_t)(m0 + r) * CDIM + c4);
    }

    for (int c = 0; c < 6; c++) {
        const int k0 = c * 64;

        // ---- STS X (split hi/lo, swizzled) from prefetched regs ----
        #pragma unroll
        for (int rep = 0; rep < 8; rep++) {
            int id = tid + rep * 256;
            int r  = id >> 4;
            int c4 = (id & 15) * 4;
            uint32_t h01, l01, h23, l23;
            split_pair(px[rep].x, px[rep].y, h01, l01);
            split_pair(px[rep].z, px[rep].w, h23, l23);
            int off = r * 64 + (((c4 >> 3) ^ (r & 7)) << 3) + (c4 & 7);
            *(uint2*)(sXh + off) = make_uint2(h01, h23);
            *(uint2*)(sXl + off) = make_uint2(l01, l23);
        }
        // ---- LDG + STS W (split hi/lo, swizzled) ----
        #pragma unroll
        for (int mm = 0; mm < 3; mm++) {
            #pragma unroll
            for (int rep = 0; rep < 4; rep++) {
                int id = tid + rep * 256;
                int r  = id >> 4;
                int c4 = (id & 15) * 4;
                float4 v = *(const float4*)(Wmat[mm] + (size_t)(k0 + r) * HDIM + c4);
                uint32_t h01, l01, h23, l23;
                split_pair(v.x, v.y, h01, l01);
                split_pair(v.z, v.w, h23, l23);
                int colh = mm * 64 + c4;
                int off  = r * 192 + ((((colh >> 3)) ^ (r & 7)) << 3) + (colh & 7);
                *(uint2*)(sWh + off) = make_uint2(h01, h23);
                *(uint2*)(sWl + off) = make_uint2(l01, l23);
            }
        }
        __syncthreads();

        // ---- prefetch next X chunk (LDG overlapped with MMA below) ----
        if (c < 5) {
            #pragma unroll
            for (int rep = 0; rep < 8; rep++) {
                int id = tid + rep * 256;
                int r  = id >> 4;
                int c4 = (id & 15) * 4;
                px[rep] = *(const float4*)(x + (size_t)(m0 + r) * CDIM + k0 + 64 + c4);
            }
        }

        // ---- MMA: 4 k-steps of 16, split-precision 3 passes ----
        #pragma unroll
        for (int ks = 0; ks < 4; ks++) {
            uint32_t aXh[2][4], aXl[2][4];
            #pragma unroll
            for (int mt = 0; mt < 2; mt++) {
                int arow = wrow0 + mt * 16 + lr + ((mat & 1) << 3);
                int kb   = ks * 2 + (mat >> 1);
                int aoff = arow * 64 + ((kb ^ (arow & 7)) << 3);
                ldsm_x4(aXh[mt], smem_u32(sXh + aoff));
                ldsm_x4(aXl[mt], smem_u32(sXl + aoff));
            }
            #pragma unroll
            for (int nb = 0; nb < 6; nb++) {
                int brow = ks * 16 + lr + ((mat & 1) << 3);
                int cbg  = wn * 12 + nb * 2 + (mat >> 1);
                int boff = brow * 192 + ((cbg ^ (brow & 7)) << 3);
                uint32_t bh[4], bl[4];
                ldsm_x4_t(bh, smem_u32(sWh + boff));
                ldsm_x4_t(bl, smem_u32(sWl + boff));
                #pragma unroll
                for (int mt = 0; mt < 2; mt++) {
                    mma_f16(C[mt][2 * nb],     aXh[mt], bh[0], bh[1]);
                    mma_f16(C[mt][2 * nb],     aXh[mt], bl[0], bl[1]);
                    mma_f16(C[mt][2 * nb],     aXl[mt], bh[0], bh[1]);
                    mma_f16(C[mt][2 * nb + 1], aXh[mt], bh[2], bh[3]);
                    mma_f16(C[mt][2 * nb + 1], aXh[mt], bl[2], bl[3]);
                    mma_f16(C[mt][2 * nb + 1], aXl[mt], bh[2], bh[3]);
                }
            }
        }
        __syncthreads();
    }

    // ---- epilogue: scale q, store (q,v hi-only; k hi+lo) ----
    #pragma unroll
    for (int mt = 0; mt < 2; mt++) {
        #pragma unroll
        for (int nf = 0; nf < 12; nf++) {
            int col = wn * 96 + nf * 8 + tig * 2;
            int mm  = col >> 6;
            int cin = col & 63;
            float s = (mm == 0) ? 0.125f : 1.f;
            size_t r0 = (size_t)(m0 + wrow0 + mt * 16 + g);
            uint32_t h01, l01, h23, l23;
            split_pair(C[mt][nf][0] * s, C[mt][nf][1] * s, h01, l01);
            split_pair(C[mt][nf][2] * s, C[mt][nf][3] * s, h23, l23);
            __half* ohp = (mm == 0) ? g_qh : ((mm == 1) ? g_kh : g_vh);
            *(uint32_t*)(ohp + r0 * 64 + cin)       = h01;
            *(uint32_t*)(ohp + (r0 + 8) * 64 + cin) = h23;
            if (mm == 1) {
                *(uint32_t*)(g_kl + r0 * 64 + cin)       = l01;
                *(uint32_t*)(g_kl + (r0 + 8) * 64 + cin) = l23;
            }
        }
    }
}

// ---------------------------------------------------------------------------
// Kernel 2: warp-MMA flash attention, cp.async double-buffered {Kh,Kl,Vh}.
// Block: 256 threads / 8 warps, 128 q-rows (16 per warp), 64-key tiles.
// S = Qh.Kh + Qh.Kl ; P split in-register ; O += Ph.Vh + Pl.Vh.
// Smem: 2 x 24KB buffers (48KB dynamic); 2 CTAs/SM forced.
// ---------------------------------------------------------------------------
__global__ __launch_bounds__(256, 2) void attn_mma_kernel(float* __restrict__ out)
{
    extern __shared__ __half smp[];
    const uint32_t sbase = smem_u32(smp);

    const int b    = blockIdx.y;
    const int qt   = (int)gridDim.x - 1 - (int)blockIdx.x;   // heavy blocks first
    const int tid  = threadIdx.x;
    const int lane = tid & 31;
    const int w    = tid >> 5;
    const int g    = lane >> 2;
    const int tig  = lane & 3;
    const int lr   = lane & 7;
    const int mat  = lane >> 3;
    const float NEG = __int_as_float(0xff800000);

    const int row0_g = qt * 128 + w * 16 + g;
    const int row1_g = row0_g + 8;

    // ---- Stage Q hi through buffer 0, preload A fragments ----
    uint32_t aQh[4][4];
    {
        __half* sQ = smp;
        const int qrow = w * 16 + lr + ((mat & 1) << 3);
        const __half* gqh = g_qh + ((size_t)b * SEQ + qt * 128) * HDIM;

        for (int i = tid; i < 128 * 8; i += 256) {
            int r = i >> 3, cb = i & 7;
            *(uint4*)(sQ + r * 64 + ((cb ^ (r & 7)) << 3)) =
                *(const uint4*)(gqh + r * 64 + (cb << 3));
        }
        __syncthreads();
        #pragma unroll
        for (int kc = 0; kc < 4; kc++) {
            int cb = kc * 2 + (mat >> 1);
            ldsm_x4(aQh[kc], smem_u32(sQ + qrow * 64 + ((cb ^ (qrow & 7)) << 3)));
        }
        __syncthreads();    // fragments read before cp.async overwrites buf0
    }

    float Oacc[8][4];
    #pragma unroll
    for (int nh = 0; nh < 8; nh++)
        #pragma unroll
        for (int c = 0; c < 4; c++) Oacc[nh][c] = 0.f;
    float m0 = NEG, m1 = NEG, l0 = 0.f, l1 = 0.f;

    const int nkt = 2 * qt + 2;
    const size_t bbase = (size_t)b * SEQ * HDIM;

    // ---- prologue: async-load tile 0 into buffer 0 ----
    {
        const __half* pkh = g_kh + bbase;
        const __half* pkl = g_kl + bbase;
        const __half* pvh = g_vh + bbase;
        #pragma unroll
        for (int rep = 0; rep < 2; rep++) {
            int i  = tid + rep * 256;
            int r  = i >> 3, cb = i & 7;
            uint32_t so = (uint32_t)(r * 64 + ((cb ^ (r & 7)) << 3)) * 2;
            int go = r * 64 + cb * 8;
            cp_async16(sbase + 0     + so, pkh + go);
            cp_async16(sbase + 8192  + so, pkl + go);
            cp_async16(sbase + 16384 + so, pvh + go);
        }
        CP_COMMIT();
    }

    for (int kt = 0; kt < nkt; kt++) {
        const int cur = kt & 1;
        const int nxt = cur ^ 1;

        // ---- prefetch tile kt+1 into other buffer ----
        if (kt + 1 < nkt) {
            const size_t tb = bbase + (size_t)(kt + 1) * 64 * HDIM;
            const __half* pkh = g_kh + tb;
            const __half* pkl = g_kl + tb;
            const __half* pvh = g_vh + tb;
            const uint32_t db = sbase + (uint32_t)nxt * 24576u;
            #pragma unroll
            for (int rep = 0; rep < 2; rep++) {
                int i  = tid + rep * 256;
                int r  = i >> 3, cb = i & 7;
                uint32_t so = (uint32_t)(r * 64 + ((cb ^ (r & 7)) << 3)) * 2;
                int go = r * 64 + cb * 8;
                cp_async16(db + 0     + so, pkh + go);
                cp_async16(db + 8192  + so, pkl + go);
                cp_async16(db + 16384 + so, pvh + go);
            }
        }
        CP_COMMIT();
        CP_WAIT1();            // tile kt's group complete
        __syncthreads();

        const __half* sKh = smp + cur * 12288;
        const __half* sKl = sKh + 4096;
        const __half* sVh = sKh + 8192;
        const int j0 = kt * 64;

        // ---- S = Qh.K^T (2-pass: Kh + Kl), fp32 accum ----
        float sacc[8][4];
        #pragma unroll
        for (int nt = 0; nt < 8; nt++)
            #pragma unroll
            for (int c = 0; c < 4; c++) sacc[nt][c] = 0.f;

        #pragma unroll
        for (int kp = 0; kp < 2; kp++) {
            #pragma unroll
            for (int nt = 0; nt < 8; nt++) {
                int krow = nt * 8 + lr;
                int cb   = kp * 4 + mat;
                int soff = krow * 64 + ((cb ^ (krow & 7)) << 3);
                uint32_t bh[4], bl[4];
                ldsm_x4(bh, smem_u32(sKh + soff));
                ldsm_x4(bl, smem_u32(sKl + soff));
                mma_f16(sacc[nt], aQh[2 * kp],     bh[0], bh[1]);
                mma_f16(sacc[nt], aQh[2 * kp],     bl[0], bl[1]);
                mma_f16(sacc[nt], aQh[2 * kp + 1], bh[2], bh[3]);
                mma_f16(sacc[nt], aQh[2 * kp + 1], bl[2], bl[3]);
            }
        }

        // ---- causal mask + online softmax (2 rows per thread) ----
        float mt0 = NEG, mt1 = NEG;
        #pragma unroll
        for (int nt = 0; nt < 8; nt++) {
            int j = j0 + nt * 8 + tig * 2;
            sacc[nt][0] = (j     <= row0_g) ? sacc[nt][0] : NEG;
            sacc[nt][1] = (j + 1 <= row0_g) ? sacc[nt][1] : NEG;
            sacc[nt][2] = (j     <= row1_g) ? sacc[nt][2] : NEG;
            sacc[nt][3] = (j + 1 <= row1_g) ? sacc[nt][3] : NEG;
            mt0 = fmaxf(mt0, fmaxf(sacc[nt][0], sacc[nt][1]));
            mt1 = fmaxf(mt1, fmaxf(sacc[nt][2], sacc[nt][3]));
        }
        mt0 = fmaxf(mt0, __shfl_xor_sync(0xffffffffu, mt0, 1));
        mt0 = fmaxf(mt0, __shfl_xor_sync(0xffffffffu, mt0, 2));
        mt1 = fmaxf(mt1, __shfl_xor_sync(0xffffffffu, mt1, 1));
        mt1 = fmaxf(mt1, __shfl_xor_sync(0xffffffffu, mt1, 2));

        const float mn0 = fmaxf(m0, mt0);
        const float mn1 = fmaxf(m1, mt1);
        const float cr0 = __expf(m0 - mn0);
        const float cr1 = __expf(m1 - mn1);
        m0 = mn0; m1 = mn1;

        float ls0 = 0.f, ls1 = 0.f;
        #pragma unroll
        for (int nt = 0; nt < 8; nt++) {
            sacc[nt][0] = __expf(sacc[nt][0] - mn0);
            sacc[nt][1] = __expf(sacc[nt][1] - mn0);
            sacc[nt][2] = __expf(sacc[nt][2] - mn1);
            sacc[nt][3] = __expf(sacc[nt][3] - mn1);
            ls0 += sacc[nt][0] + sacc[nt][1];
            ls1 += sacc[nt][2] + sacc[nt][3];
        }
        l0 = l0 * cr0 + ls0;
        l1 = l1 * cr1 + ls1;

        #pragma unroll
        for (int nh = 0; nh < 8; nh++) {
            Oacc[nh][0] *= cr0; Oacc[nh][1] *= cr0;
            Oacc[nh][2] *= cr1; Oacc[nh][3] *= cr1;
        }

        // ---- O += P.Vh (P split: Ph + Pl passes) ----
        #pragma unroll
        for (int kc = 0; kc < 4; kc++) {
            uint32_t aPh[4], aPl[4];
            split_pair(sacc[2 * kc][0],     sacc[2 * kc][1],     aPh[0], aPl[0]);
            split_pair(sacc[2 * kc][2],     sacc[2 * kc][3],     aPh[1], aPl[1]);
            split_pair(sacc[2 * kc + 1][0], sacc[2 * kc + 1][1], aPh[2], aPl[2]);
            split_pair(sacc[2 * kc + 1][2], sacc[2 * kc + 1][3], aPh[3], aPl[3]);

            #pragma unroll
            for (int np = 0; np < 4; np++) {
                int vrow = kc * 16 + lr + ((mat & 1) << 3);
                int cb   = np * 2 + (mat >> 1);
                int soff = vrow * 64 + ((cb ^ (vrow & 7)) << 3);
                uint32_t bh[4];
                ldsm_x4_t(bh, smem_u32(sVh + soff));
                mma_f16(Oacc[2 * np],     aPh, bh[0], bh[1]);
                mma_f16(Oacc[2 * np],     aPl, bh[0], bh[1]);
                mma_f16(Oacc[2 * np + 1], aPh, bh[2], bh[3]);
                mma_f16(Oacc[2 * np + 1], aPl, bh[2], bh[3]);
            }
        }
        __syncthreads();     // buffer cur fully consumed before it is refilled
    }

    // ---- epilogue: finish row sums, normalize, store ----
    l0 += __shfl_xor_sync(0xffffffffu, l0, 1);
    l0 += __shfl_xor_sync(0xffffffffu, l0, 2);
    l1 += __shfl_xor_sync(0xffffffffu, l1, 1);
    l1 += __shfl_xor_sync(0xffffffffu, l1, 2);
    const float inv0 = 1.f / l0;
    const float inv1 = 1.f / l1;

    float* po = out + (size_t)b * SEQ * HDIM;
    #pragma unroll
    for (int nh = 0; nh < 8; nh++) {
        int c = nh * 8 + tig * 2;
        *(float2*)(po + (size_t)row0_g * HDIM + c) =
            make_float2(Oacc[nh][0] * inv0, Oacc[nh][1] * inv0);
        *(float2*)(po + (size_t)row1_g * HDIM + c) =
            make_float2(Oacc[nh][2] * inv1, Oacc[nh][3] * inv1);
    }
}

// ---------------------------------------------------------------------------
extern "C" void kernel_launch(void* const* d_in, const int* in_sizes, int n_in,
                              void* d_out, int out_size)
{
    const float* x  = (const float*)d_in[0];
    const float* Wk = (const float*)d_in[1];
    const float* Wq = (const float*)d_in[2];
    const float* Wv = (const float*)d_in[3];
    float* out = (float*)d_out;

    (void)in_sizes; (void)n_in; (void)out_size;

    cudaFuncSetAttribute(qkv_mma_kernel,
                         cudaFuncAttributeMaxDynamicSharedMemorySize, 81920);
    cudaFuncSetAttribute(attn_mma_kernel,
                         cudaFuncAttributeMaxDynamicSharedMemorySize, 49152);

    qkv_mma_kernel<<<BT / 128, 256, 81920>>>(x, Wk, Wq, Wv);
    attn_mma_kernel<<<dim3(SEQ / 128, BATCH), 256, 49152>>>(out);
}

// round 13
// speedup vs baseline: 8.2971x; 1.1822x over previous
#include <cuda_runtime.h>
#include <cuda_fp16.h>
#include <math.h>
#include <stdint.h>

// Problem constants
#define BATCH 32
#define SEQ   2048
#define CDIM  384
#define HDIM  64
#define BT    (BATCH * SEQ)

// Projected q,k,v (fp16 hi parts only; q pre-scaled by H^{-1/2}*log2(e))
__device__ __half g_qh[BT * HDIM];
__device__ __half g_kh[BT * HDIM];
__device__ __half g_vh[BT * HDIM];

// ===========================================================================
// Warp-MMA helpers (sm_80+ baseline PTX)
// ===========================================================================
__device__ __forceinline__ uint32_t smem_u32(const void* p) {
    uint32_t a;
    asm("{ .reg .u64 t; cvta.to.shared.u64 t, %1; cvt.u32.u64 %0, t; }"
        : "=r"(a) : "l"(p));
    return a;
}

__device__ __forceinline__ void ldsm_x4(uint32_t* r, uint32_t a) {
    asm volatile("ldmatrix.sync.aligned.m8n8.x4.shared.b16 {%0,%1,%2,%3}, [%4];"
                 : "=r"(r[0]), "=r"(r[1]), "=r"(r[2]), "=r"(r[3]) : "r"(a));
}
__device__ __forceinline__ void ldsm_x4_t(uint32_t* r, uint32_t a) {
    asm volatile("ldmatrix.sync.aligned.m8n8.x4.trans.shared.b16 {%0,%1,%2,%3}, [%4];"
                 : "=r"(r[0]), "=r"(r[1]), "=r"(r[2]), "=r"(r[3]) : "r"(a));
}

__device__ __forceinline__ void mma_f16(float* c, const uint32_t* a,
                                        uint32_t b0, uint32_t b1) {
    asm volatile(
        "mma.sync.aligned.m16n8k16.row.col.f32.f16.f16.f32 "
        "{%0,%1,%2,%3}, {%4,%5,%6,%7}, {%8,%9}, {%0,%1,%2,%3};"
        : "+f"(c[0]), "+f"(c[1]), "+f"(c[2]), "+f"(c[3])
        : "r"(a[0]), "r"(a[1]), "r"(a[2]), "r"(a[3]), "r"(b0), "r"(b1));
}

__device__ __forceinline__ void cp_async16(uint32_t dst, const void* src) {
    asm volatile("cp.async.cg.shared.global [%0], [%1], 16;" :: "r"(dst), "l"(src));
}
#define CP_COMMIT() asm volatile("cp.async.commit_group;" ::: "memory")
#define CP_WAIT1()  asm volatile("cp.async.wait_group 1;" ::: "memory")

__device__ __forceinline__ float fast_exp2(float x) {
    float y;
    asm("ex2.approx.ftz.f32 %0, %1;" : "=f"(y) : "f"(x));
    return y;
}

__device__ __forceinline__ uint32_t pack_h2(__half x, __half y) {
    __half2 t = __halves2half2(x, y);
    return *(uint32_t*)&t;
}

// Split a float pair into packed fp16 hi and lo words.
__device__ __forceinline__ void split_pair(float x, float y,
                                           uint32_t& hi, uint32_t& lo) {
    __half hx = __float2half(x);
    __half hy = __float2half(y);
    __half lx = __float2half(x - __half2float(hx));
    __half ly = __float2half(y - __half2float(hy));
    hi = pack_h2(hx, hy);
    lo = pack_h2(lx, ly);
}

// ---------------------------------------------------------------------------
// Kernel 1: fused QKV projection via split-fp16 HMMA (3-pass, full precision
// inside the GEMM). Block: 256 thr / 8 warps, tile 128 x 192 (3 mats x 64).
// Epilogue: q scaled by H^{-1/2}*log2(e); all outputs stored hi-only.
// ---------------------------------------------------------------------------
__global__ __launch_bounds__(256) void qkv_mma_kernel(
    const float* __restrict__ x,
    const float* __restrict__ Wk,
    const float* __restrict__ Wq,
    const float* __restrict__ Wv)
{
    extern __shared__ __half smp[];
    __half* sXh = smp;                 // 128 x 64 halves (8192)
    __half* sXl = smp + 8192;
    __half* sWh = smp + 16384;         // 64 x 192 halves (12288)
    __half* sWl = smp + 28672;

    const int m0   = blockIdx.x * 128;
    const int tid  = threadIdx.x;
    const int lane = tid & 31;
    const int w    = tid >> 5;
    const int wm   = w >> 1;           // 0..3
    const int wn   = w & 1;            // 0..1
    const int wrow0 = wm * 32;
    const int lr   = lane & 7;
    const int mat  = lane >> 3;
    const int g    = lane >> 2;
    const int tig  = lane & 3;

    const float* Wmat[3] = {Wq, Wk, Wv};

    float C[2][12][4];
    #pragma unroll
    for (int mt = 0; mt < 2; mt++)
        #pragma unroll
        for (int nf = 0; nf < 12; nf++)
            #pragma unroll
            for (int c = 0; c < 4; c++) C[mt][nf][c] = 0.f;

    // prefetch X chunk 0 into registers
    float4 px[8];
    #pragma unroll
    for (int rep = 0; rep < 8; rep++) {
        int id = tid + rep * 256;
        int r  = id >> 4;
        int c4 = (id & 15) * 4;
        px[rep] = *(const float4*)(x + (size_t)(m0 + r) * CDIM + c4);
    }

    for (int c = 0; c < 6; c++) {
        const int k0 = c * 64;

        // ---- STS X (split hi/lo, swizzled) from prefetched regs ----
        #pragma unroll
        for (int rep = 0; rep < 8; rep++) {
            int id = tid + rep * 256;
            int r  = id >> 4;
            int c4 = (id & 15) * 4;
            uint32_t h01, l01, h23, l23;
            split_pair(px[rep].x, px[rep].y, h01, l01);
            split_pair(px[rep].z, px[rep].w, h23, l23);
            int off = r * 64 + (((c4 >> 3) ^ (r & 7)) << 3) + (c4 & 7);
            *(uint2*)(sXh + off) = make_uint2(h01, h23);
            *(uint2*)(sXl + off) = make_uint2(l01, l23);
        }
        // ---- LDG + STS W (split hi/lo, swizzled) ----
        #pragma unroll
        for (int mm = 0; mm < 3; mm++) {
            #pragma unroll
            for (int rep = 0; rep < 4; rep++) {
                int id = tid + rep * 256;
                int r  = id >> 4;
                int c4 = (id & 15) * 4;
                float4 v = *(const float4*)(Wmat[mm] + (size_t)(k0 + r) * HDIM + c4);
                uint32_t h01, l01, h23, l23;
                split_pair(v.x, v.y, h01, l01);
                split_pair(v.z, v.w, h23, l23);
                int colh = mm * 64 + c4;
                int off  = r * 192 + ((((colh >> 3)) ^ (r & 7)) << 3) + (colh & 7);
                *(uint2*)(sWh + off) = make_uint2(h01, h23);
                *(uint2*)(sWl + off) = make_uint2(l01, l23);
            }
        }
        __syncthreads();

        // ---- prefetch next X chunk (LDG overlapped with MMA below) ----
        if (c < 5) {
            #pragma unroll
            for (int rep = 0; rep < 8; rep++) {
                int id = tid + rep * 256;
                int r  = id >> 4;
                int c4 = (id & 15) * 4;
                px[rep] = *(const float4*)(x + (size_t)(m0 + r) * CDIM + k0 + 64 + c4);
            }
        }

        // ---- MMA: 4 k-steps of 16, split-precision 3 passes ----
        #pragma unroll
        for (int ks = 0; ks < 4; ks++) {
            uint32_t aXh[2][4], aXl[2][4];
            #pragma unroll
            for (int mt = 0; mt < 2; mt++) {
                int arow = wrow0 + mt * 16 + lr + ((mat & 1) << 3);
                int kb   = ks * 2 + (mat >> 1);
                int aoff = arow * 64 + ((kb ^ (arow & 7)) << 3);
                ldsm_x4(aXh[mt], smem_u32(sXh + aoff));
                ldsm_x4(aXl[mt], smem_u32(sXl + aoff));
            }
            #pragma unroll
            for (int nb = 0; nb < 6; nb++) {
                int brow = ks * 16 + lr + ((mat & 1) << 3);
                int cbg  = wn * 12 + nb * 2 + (mat >> 1);
                int boff = brow * 192 + ((cbg ^ (brow & 7)) << 3);
                uint32_t bh[4], bl[4];
                ldsm_x4_t(bh, smem_u32(sWh + boff));
                ldsm_x4_t(bl, smem_u32(sWl + boff));
                #pragma unroll
                for (int mt = 0; mt < 2; mt++) {
                    mma_f16(C[mt][2 * nb],     aXh[mt], bh[0], bh[1]);
                    mma_f16(C[mt][2 * nb],     aXh[mt], bl[0], bl[1]);
                    mma_f16(C[mt][2 * nb],     aXl[mt], bh[0], bh[1]);
                    mma_f16(C[mt][2 * nb + 1], aXh[mt], bh[2], bh[3]);
                    mma_f16(C[mt][2 * nb + 1], aXh[mt], bl[2], bl[3]);
                    mma_f16(C[mt][2 * nb + 1], aXl[mt], bh[2], bh[3]);
                }
            }
        }
        __syncthreads();
    }

    // ---- epilogue: scale q (with log2e folded), store hi parts ----
    const float QSCL = 0.125f * 1.4426950408889634f;   // H^{-1/2} * log2(e)
    #pragma unroll
    for (int mt = 0; mt < 2; mt++) {
        #pragma unroll
        for (int nf = 0; nf < 12; nf++) {
            int col = wn * 96 + nf * 8 + tig * 2;
            int mm  = col >> 6;
            int cin = col & 63;
            float s = (mm == 0) ? QSCL : 1.f;
            size_t r0 = (size_t)(m0 + wrow0 + mt * 16 + g);
            uint32_t h01 = pack_h2(__float2half(C[mt][nf][0] * s),
                                   __float2half(C[mt][nf][1] * s));
            uint32_t h23 = pack_h2(__float2half(C[mt][nf][2] * s),
                                   __float2half(C[mt][nf][3] * s));
            __half* ohp = (mm == 0) ? g_qh : ((mm == 1) ? g_kh : g_vh);
            *(uint32_t*)(ohp + r0 * 64 + cin)       = h01;
            *(uint32_t*)(ohp + (r0 + 8) * 64 + cin) = h23;
        }
    }
}

// ---------------------------------------------------------------------------
// Kernel 2: warp-MMA flash attention, cp.async double-buffered {Kh,Vh}.
// Block: 256 threads / 8 warps, 128 q-rows (16 per warp), 64-key tiles.
// S = Qh.Kh (fp32 accum, log2 domain) ; P split ; O += Ph.Vh + Pl.Vh.
// Smem: 2 x 16KB buffers (32KB dynamic); 2 CTAs/SM forced.
// ---------------------------------------------------------------------------
__global__ __launch_bounds__(256, 2) void attn_mma_kernel(float* __restrict__ out)
{
    extern __shared__ __half smp[];
    const uint32_t sbase = smem_u32(smp);

    const int b    = blockIdx.y;
    const int qt   = (int)gridDim.x - 1 - (int)blockIdx.x;   // heavy blocks first
    const int tid  = threadIdx.x;
    const int lane = tid & 31;
    const int w    = tid >> 5;
    const int g    = lane >> 2;
    const int tig  = lane & 3;
    const int lr   = lane & 7;
    const int mat  = lane >> 3;
    const float NEG = __int_as_float(0xff800000);

    const int row0_g = qt * 128 + w * 16 + g;
    const int row1_g = row0_g + 8;

    // ---- Stage Q hi through buffer 0, preload A fragments ----
    uint32_t aQh[4][4];
    {
        __half* sQ = smp;
        const int qrow = w * 16 + lr + ((mat & 1) << 3);
        const __half* gqh = g_qh + ((size_t)b * SEQ + qt * 128) * HDIM;

        for (int i = tid; i < 128 * 8; i += 256) {
            int r = i >> 3, cb = i & 7;
            *(uint4*)(sQ + r * 64 + ((cb ^ (r & 7)) << 3)) =
                *(const uint4*)(gqh + r * 64 + (cb << 3));
        }
        __syncthreads();
        #pragma unroll
        for (int kc = 0; kc < 4; kc++) {
            int cb = kc * 2 + (mat >> 1);
            ldsm_x4(aQh[kc], smem_u32(sQ + qrow * 64 + ((cb ^ (qrow & 7)) << 3)));
        }
        __syncthreads();    // fragments read before cp.async overwrites buf0
    }

    float Oacc[8][4];
    #pragma unroll
    for (int nh = 0; nh < 8; nh++)
        #pragma unroll
        for (int c = 0; c < 4; c++) Oacc[nh][c] = 0.f;
    float m0 = NEG, m1 = NEG, l0 = 0.f, l1 = 0.f;

    const int nkt = 2 * qt + 2;
    const size_t bbase = (size_t)b * SEQ * HDIM;

    // ---- prologue: async-load tile 0 into buffer 0 ----
    {
        const __half* pkh = g_kh + bbase;
        const __half* pvh = g_vh + bbase;
        #pragma unroll
        for (int rep = 0; rep < 2; rep++) {
            int i  = tid + rep * 256;
            int r  = i >> 3, cb = i & 7;
            uint32_t so = (uint32_t)(r * 64 + ((cb ^ (r & 7)) << 3)) * 2;
            int go = r * 64 + cb * 8;
            cp_async16(sbase + 0    + so, pkh + go);
            cp_async16(sbase + 8192 + so, pvh + go);
        }
        CP_COMMIT();
    }

    for (int kt = 0; kt < nkt; kt++) {
        const int cur = kt & 1;
        const int nxt = cur ^ 1;

        // ---- prefetch tile kt+1 into other buffer ----
        if (kt + 1 < nkt) {
            const size_t tb = bbase + (size_t)(kt + 1) * 64 * HDIM;
            const __half* pkh = g_kh + tb;
            const __half* pvh = g_vh + tb;
            const uint32_t db = sbase + (uint32_t)nxt * 16384u;
            #pragma unroll
            for (int rep = 0; rep < 2; rep++) {
                int i  = tid + rep * 256;
                int r  = i >> 3, cb = i & 7;
                uint32_t so = (uint32_t)(r * 64 + ((cb ^ (r & 7)) << 3)) * 2;
                int go = r * 64 + cb * 8;
                cp_async16(db + 0    + so, pkh + go);
                cp_async16(db + 8192 + so, pvh + go);
            }
        }
        CP_COMMIT();
        CP_WAIT1();            // tile kt's group complete
        __syncthreads();

        const __half* sKh = smp + cur * 8192;
        const __half* sVh = sKh + 4096;
        const int j0 = kt * 64;

        // ---- S = Qh.Kh^T (single pass, fp32 accum, log2 domain) ----
        float sacc[8][4];
        #pragma unroll
        for (int nt = 0; nt < 8; nt++)
            #pragma unroll
            for (int c = 0; c < 4; c++) sacc[nt][c] = 0.f;

        #pragma unroll
        for (int kp = 0; kp < 2; kp++) {
            #pragma unroll
            for (int nt = 0; nt < 8; nt++) {
                int krow = nt * 8 + lr;
                int cb   = kp * 4 + mat;
                int soff = krow * 64 + ((cb ^ (krow & 7)) << 3);
                uint32_t bh[4];
                ldsm_x4(bh, smem_u32(sKh + soff));
                mma_f16(sacc[nt], aQh[2 * kp],     bh[0], bh[1]);
                mma_f16(sacc[nt], aQh[2 * kp + 1], bh[2], bh[3]);
            }
        }

        // ---- causal mask + online softmax (log2 domain, 2 rows/thread) ----
        float mt0 = NEG, mt1 = NEG;
        #pragma unroll
        for (int nt = 0; nt < 8; nt++) {
            int j = j0 + nt * 8 + tig * 2;
            sacc[nt][0] = (j     <= row0_g) ? sacc[nt][0] : NEG;
            sacc[nt][1] = (j + 1 <= row0_g) ? sacc[nt][1] : NEG;
            sacc[nt][2] = (j     <= row1_g) ? sacc[nt][2] : NEG;
            sacc[nt][3] = (j + 1 <= row1_g) ? sacc[nt][3] : NEG;
            mt0 = fmaxf(mt0, fmaxf(sacc[nt][0], sacc[nt][1]));
            mt1 = fmaxf(mt1, fmaxf(sacc[nt][2], sacc[nt][3]));
        }
        mt0 = fmaxf(mt0, __shfl_xor_sync(0xffffffffu, mt0, 1));
        mt0 = fmaxf(mt0, __shfl_xor_sync(0xffffffffu, mt0, 2));
        mt1 = fmaxf(mt1, __shfl_xor_sync(0xffffffffu, mt1, 1));
        mt1 = fmaxf(mt1, __shfl_xor_sync(0xffffffffu, mt1, 2));

        const float mn0 = fmaxf(m0, mt0);
        const float mn1 = fmaxf(m1, mt1);
        const float cr0 = fast_exp2(m0 - mn0);
        const float cr1 = fast_exp2(m1 - mn1);
        m0 = mn0; m1 = mn1;

        float ls0 = 0.f, ls1 = 0.f;
        #pragma unroll
        for (int nt = 0; nt < 8; nt++) {
            sacc[nt][0] = fast_exp2(sacc[nt][0] - mn0);
            sacc[nt][1] = fast_exp2(sacc[nt][1] - mn0);
            sacc[nt][2] = fast_exp2(sacc[nt][2] - mn1);
            sacc[nt][3] = fast_exp2(sacc[nt][3] - mn1);
            ls0 += sacc[nt][0] + sacc[nt][1];
            ls1 += sacc[nt][2] + sacc[nt][3];
        }
        l0 = l0 * cr0 + ls0;
        l1 = l1 * cr1 + ls1;

        #pragma unroll
        for (int nh = 0; nh < 8; nh++) {
            Oacc[nh][0] *= cr0; Oacc[nh][1] *= cr0;
            Oacc[nh][2] *= cr1; Oacc[nh][3] *= cr1;
        }

        // ---- O += P.Vh (P split: Ph + Pl passes) ----
        #pragma unroll
        for (int kc = 0; kc < 4; kc++) {
            uint32_t aPh[4], aPl[4];
            split_pair(sacc[2 * kc][0],     sacc[2 * kc][1],     aPh[0], aPl[0]);
            split_pair(sacc[2 * kc][2],     sacc[2 * kc][3],     aPh[1], aPl[1]);
            split_pair(sacc[2 * kc + 1][0], sacc[2 * kc + 1][1], aPh[2], aPl[2]);
            split_pair(sacc[2 * kc + 1][2], sacc[2 * kc + 1][3], aPh[3], aPl[3]);

            #pragma unroll
            for (int np = 0; np < 4; np++) {
                int vrow = kc * 16 + lr + ((mat & 1) << 3);
                int cb   = np * 2 + (mat >> 1);
                int soff = vrow * 64 + ((cb ^ (vrow & 7)) << 3);
                uint32_t bh[4];
                ldsm_x4_t(bh, smem_u32(sVh + soff));
                mma_f16(Oacc[2 * np],     aPh, bh[0], bh[1]);
                mma_f16(Oacc[2 * np],     aPl, bh[0], bh[1]);
                mma_f16(Oacc[2 * np + 1], aPh, bh[2], bh[3]);
                mma_f16(Oacc[2 * np + 1], aPl, bh[2], bh[3]);
            }
        }
        __syncthreads();     // buffer cur fully consumed before it is refilled
    }

    // ---- epilogue: finish row sums, normalize, store ----
    l0 += __shfl_xor_sync(0xffffffffu, l0, 1);
    l0 += __shfl_xor_sync(0xffffffffu, l0, 2);
    l1 += __shfl_xor_sync(0xffffffffu, l1, 1);
    l1 += __shfl_xor_sync(0xffffffffu, l1, 2);
    const float inv0 = 1.f / l0;
    const float inv1 = 1.f / l1;

    float* po = out + (size_t)b * SEQ * HDIM;
    #pragma unroll
    for (int nh = 0; nh < 8; nh++) {
        int c = nh * 8 + tig * 2;
        *(float2*)(po + (size_t)row0_g * HDIM + c) =
            make_float2(Oacc[nh][0] * inv0, Oacc[nh][1] * inv0);
        *(float2*)(po + (size_t)row1_g * HDIM + c) =
            make_float2(Oacc[nh][2] * inv1, Oacc[nh][3] * inv1);
    }
}

// ---------------------------------------------------------------------------
extern "C" void kernel_launch(void* const* d_in, const int* in_sizes, int n_in,
                              void* d_out, int out_size)
{
    const float* x  = (const float*)d_in[0];
    const float* Wk = (const float*)d_in[1];
    const float* Wq = (const float*)d_in[2];
    const float* Wv = (const float*)d_in[3];
    float* out = (float*)d_out;

    (void)in_sizes; (void)n_in; (void)out_size;

    cudaFuncSetAttribute(qkv_mma_kernel,
                         cudaFuncAttributeMaxDynamicSharedMemorySize, 81920);
    cudaFuncSetAttribute(attn_mma_kernel,
                         cudaFuncAttributeMaxDynamicSharedMemorySize, 32768);

    qkv_mma_kernel<<<BT / 128, 256, 81920>>>(x, Wk, Wq, Wv);
    attn_mma_kernel<<<dim3(SEQ / 128, BATCH), 256, 32768>>>(out);
}

// round 15
// speedup vs baseline: 9.5530x; 1.1514x over previous
#include <cuda_runtime.h>
#include <cuda_fp16.h>
#include <math.h>
#include <stdint.h>

// Problem constants
#define BATCH 32
#define SEQ   2048
#define CDIM  384
#define HDIM  64
#define BT    (BATCH * SEQ)

// Projected q,k,v (fp16 hi parts only; q pre-scaled by H^{-1/2}*log2(e))
__device__ __half g_qh[BT * HDIM];
__device__ __half g_kh[BT * HDIM];
__device__ __half g_vh[BT * HDIM];

// ===========================================================================
// Warp-MMA helpers (sm_80+ baseline PTX)
// ===========================================================================
__device__ __forceinline__ uint32_t smem_u32(const void* p) {
    uint32_t a;
    asm("{ .reg .u64 t; cvta.to.shared.u64 t, %1; cvt.u32.u64 %0, t; }"
        : "=r"(a) : "l"(p));
    return a;
}

__device__ __forceinline__ void ldsm_x4(uint32_t* r, uint32_t a) {
    asm volatile("ldmatrix.sync.aligned.m8n8.x4.shared.b16 {%0,%1,%2,%3}, [%4];"
                 : "=r"(r[0]), "=r"(r[1]), "=r"(r[2]), "=r"(r[3]) : "r"(a));
}
__device__ __forceinline__ void ldsm_x4_t(uint32_t* r, uint32_t a) {
    asm volatile("ldmatrix.sync.aligned.m8n8.x4.trans.shared.b16 {%0,%1,%2,%3}, [%4];"
                 : "=r"(r[0]), "=r"(r[1]), "=r"(r[2]), "=r"(r[3]) : "r"(a));
}

__device__ __forceinline__ void mma_f16(float* c, const uint32_t* a,
                                        uint32_t b0, uint32_t b1) {
    asm volatile(
        "mma.sync.aligned.m16n8k16.row.col.f32.f16.f16.f32 "
        "{%0,%1,%2,%3}, {%4,%5,%6,%7}, {%8,%9}, {%0,%1,%2,%3};"
        : "+f"(c[0]), "+f"(c[1]), "+f"(c[2]), "+f"(c[3])
        : "r"(a[0]), "r"(a[1]), "r"(a[2]), "r"(a[3]), "r"(b0), "r"(b1));
}

__device__ __forceinline__ void cp_async16(uint32_t dst, const void* src) {
    asm volatile("cp.async.cg.shared.global [%0], [%1], 16;" :: "r"(dst), "l"(src));
}
#define CP_COMMIT() asm volatile("cp.async.commit_group;" ::: "memory")
#define CP_WAIT1()  asm volatile("cp.async.wait_group 1;" ::: "memory")

__device__ __forceinline__ float fast_exp2(float x) {
    float y;
    asm("ex2.approx.ftz.f32 %0, %1;" : "=f"(y) : "f"(x));
    return y;
}

__device__ __forceinline__ uint32_t pack_h2(__half x, __half y) {
    __half2 t = __halves2half2(x, y);
    return *(uint32_t*)&t;
}

// Split a float pair into packed fp16 hi and lo words.
__device__ __forceinline__ void split_pair(float x, float y,
                                           uint32_t& hi, uint32_t& lo) {
    __half hx = __float2half(x);
    __half hy = __float2half(y);
    __half lx = __float2half(x - __half2float(hx));
    __half ly = __float2half(y - __half2float(hy));
    hi = pack_h2(hx, hy);
    lo = pack_h2(ly, ly);
    lo = pack_h2(lx, ly);
}

// ---------------------------------------------------------------------------
// Kernel 1: fused QKV projection via fp16 HMMA, 2-pass (Xh.Wh + Xh.Wl).
// X stored hi-only in smem; W split hi/lo. Block: 256 thr / 8 warps,
// tile 128 x 192 (3 mats x 64). Epilogue: q scaled by H^{-1/2}*log2(e).
// ---------------------------------------------------------------------------
__global__ __launch_bounds__(256) void qkv_mma_kernel(
    const float* __restrict__ x,
    const float* __restrict__ Wk,
    const float* __restrict__ Wq,
    const float* __restrict__ Wv)
{
    extern __shared__ __half smp[];
    __half* sXh = smp;                 // 128 x 64 halves (8192)
    __half* sWh = smp + 8192;          // 64 x 192 halves (12288)
    __half* sWl = smp + 20480;

    const int m0   = blockIdx.x * 128;
    const int tid  = threadIdx.x;
    const int lane = tid & 31;
    const int w    = tid >> 5;
    const int wm   = w >> 1;           // 0..3
    const int wn   = w & 1;            // 0..1
    const int wrow0 = wm * 32;
    const int lr   = lane & 7;
    const int mat  = lane >> 3;
    const int g    = lane >> 2;
    const int tig  = lane & 3;

    const float* Wmat[3] = {Wq, Wk, Wv};

    float C[2][12][4];
    #pragma unroll
    for (int mt = 0; mt < 2; mt++)
        #pragma unroll
        for (int nf = 0; nf < 12; nf++)
            #pragma unroll
            for (int c = 0; c < 4; c++) C[mt][nf][c] = 0.f;

    // prefetch X chunk 0 into registers
    float4 px[8];
    #pragma unroll
    for (int rep = 0; rep < 8; rep++) {
        int id = tid + rep * 256;
        int r  = id >> 4;
        int c4 = (id & 15) * 4;
        px[rep] = *(const float4*)(x + (size_t)(m0 + r) * CDIM + c4);
    }

    for (int c = 0; c < 6; c++) {
        const int k0 = c * 64;

        // ---- STS X (hi only, swizzled) from prefetched regs ----
        #pragma unroll
        for (int rep = 0; rep < 8; rep++) {
            int id = tid + rep * 256;
            int r  = id >> 4;
            int c4 = (id & 15) * 4;
            uint32_t h01 = pack_h2(__float2half(px[rep].x), __float2half(px[rep].y));
            uint32_t h23 = pack_h2(__float2half(px[rep].z), __float2half(px[rep].w));
            int off = r * 64 + (((c4 >> 3) ^ (r & 7)) << 3) + (c4 & 7);
            *(uint2*)(sXh + off) = make_uint2(h01, h23);
        }
        // ---- LDG + STS W (split hi/lo, swizzled) ----
        #pragma unroll
        for (int mm = 0; mm < 3; mm++) {
            #pragma unroll
            for (int rep = 0; rep < 4; rep++) {
                int id = tid + rep * 256;
                int r  = id >> 4;
                int c4 = (id & 15) * 4;
                float4 v = *(const float4*)(Wmat[mm] + (size_t)(k0 + r) * HDIM + c4);
                uint32_t h01, l01, h23, l23;
                split_pair(v.x, v.y, h01, l01);
                split_pair(v.z, v.w, h23, l23);
                int colh = mm * 64 + c4;
                int off  = r * 192 + ((((colh >> 3)) ^ (r & 7)) << 3) + (colh & 7);
                *(uint2*)(sWh + off) = make_uint2(h01, h23);
                *(uint2*)(sWl + off) = make_uint2(l01, l23);
            }
        }
        __syncthreads();

        // ---- prefetch next X chunk (LDG overlapped with MMA below) ----
        if (c < 5) {
            #pragma unroll
            for (int rep = 0; rep < 8; rep++) {
                int id = tid + rep * 256;
                int r  = id >> 4;
                int c4 = (id & 15) * 4;
                px[rep] = *(const float4*)(x + (size_t)(m0 + r) * CDIM + k0 + 64 + c4);
            }
        }

        // ---- MMA: 4 k-steps of 16, 2 passes (Wh + Wl) ----
        #pragma unroll
        for (int ks = 0; ks < 4; ks++) {
            uint32_t aXh[2][4];
            #pragma unroll
            for (int mt = 0; mt < 2; mt++) {
                int arow = wrow0 + mt * 16 + lr + ((mat & 1) << 3);
                int kb   = ks * 2 + (mat >> 1);
                int aoff = arow * 64 + ((kb ^ (arow & 7)) << 3);
                ldsm_x4(aXh[mt], smem_u32(sXh + aoff));
            }
            #pragma unroll
            for (int nb = 0; nb < 6; nb++) {
                int brow = ks * 16 + lr + ((mat & 1) << 3);
                int cbg  = wn * 12 + nb * 2 + (mat >> 1);
                int boff = brow * 192 + ((cbg ^ (brow & 7)) << 3);
                uint32_t bh[4], bl[4];
                ldsm_x4_t(bh, smem_u32(sWh + boff));
                ldsm_x4_t(bl, smem_u32(sWl + boff));
                #pragma unroll
                for (int mt = 0; mt < 2; mt++) {
                    mma_f16(C[mt][2 * nb],     aXh[mt], bh[0], bh[1]);
                    mma_f16(C[mt][2 * nb],     aXh[mt], bl[0], bl[1]);
                    mma_f16(C[mt][2 * nb + 1], aXh[mt], bh[2], bh[3]);
                    mma_f16(C[mt][2 * nb + 1], aXh[mt], bl[2], bl[3]);
                }
            }
        }
        __syncthreads();
    }

    // ---- epilogue: scale q (with log2e folded), store hi parts ----
    const float QSCL = 0.125f * 1.4426950408889634f;   // H^{-1/2} * log2(e)
    #pragma unroll
    for (int mt = 0; mt < 2; mt++) {
        #pragma unroll
        for (int nf = 0; nf < 12; nf++) {
            int col = wn * 96 + nf * 8 + tig * 2;
            int mm  = col >> 6;
            int cin = col & 63;
            float s = (mm == 0) ? QSCL : 1.f;
            size_t r0 = (size_t)(m0 + wrow0 + mt * 16 + g);
            uint32_t h01 = pack_h2(__float2half(C[mt][nf][0] * s),
                                   __float2half(C[mt][nf][1] * s));
            uint32_t h23 = pack_h2(__float2half(C[mt][nf][2] * s),
                                   __float2half(C[mt][nf][3] * s));
            __half* ohp = (mm == 0) ? g_qh : ((mm == 1) ? g_kh : g_vh);
            *(uint32_t*)(ohp + r0 * 64 + cin)       = h01;
            *(uint32_t*)(ohp + (r0 + 8) * 64 + cin) = h23;
        }
    }
}

// ---------------------------------------------------------------------------
// Kernel 2: warp-MMA flash attention, cp.async double-buffered {Kh,Vh}.
// Block: 256 threads / 8 warps, 128 q-rows (16 per warp), 64-key tiles.
// S = Qh.Kh (fp32 accum, log2 domain) ; P split ; O += Ph.Vh + Pl.Vh.
// Causal masking applied only to the two diagonal tiles (uniform branch).
// Smem: 2 x 16KB buffers (32KB dynamic); 2 CTAs/SM forced.
// ---------------------------------------------------------------------------
__global__ __launch_bounds__(256, 2) void attn_mma_kernel(float* __restrict__ out)
{
    extern __shared__ __half smp[];
    const uint32_t sbase = smem_u32(smp);

    const int b    = blockIdx.y;
    const int qt   = (int)gridDim.x - 1 - (int)blockIdx.x;   // heavy blocks first
    const int tid  = threadIdx.x;
    const int lane = tid & 31;
    const int w    = tid >> 5;
    const int g    = lane >> 2;
    const int tig  = lane & 3;
    const int lr   = lane & 7;
    const int mat  = lane >> 3;
    const float NEG = __int_as_float(0xff800000);

    const int row0_g = qt * 128 + w * 16 + g;
    const int row1_g = row0_g + 8;

    // ---- Stage Q hi through buffer 0, preload A fragments ----
    uint32_t aQh[4][4];
    {
        __half* sQ = smp;
        const int qrow = w * 16 + lr + ((mat & 1) << 3);
        const __half* gqh = g_qh + ((size_t)b * SEQ + qt * 128) * HDIM;

        for (int i = tid; i < 128 * 8; i += 256) {
            int r = i >> 3, cb = i & 7;
            *(uint4*)(sQ + r * 64 + ((cb ^ (r & 7)) << 3)) =
                *(const uint4*)(gqh + r * 64 + (cb << 3));
        }
        __syncthreads();
        #pragma unroll
        for (int kc = 0; kc < 4; kc++) {
            int cb = kc * 2 + (mat >> 1);
            ldsm_x4(aQh[kc], smem_u32(sQ + qrow * 64 + ((cb ^ (qrow & 7)) << 3)));
        }
        __syncthreads();    // fragments read before cp.async overwrites buf0
    }

    float Oacc[8][4];
    #pragma unroll
    for (int nh = 0; nh < 8; nh++)
        #pragma unroll
        for (int c = 0; c < 4; c++) Oacc[nh][c] = 0.f;
    float m0 = NEG, m1 = NEG, l0 = 0.f, l1 = 0.f;

    const int nkt = 2 * qt + 2;
    const size_t bbase = (size_t)b * SEQ * HDIM;

    // ---- prologue: async-load tile 0 into buffer 0 ----
    {
        const __half* pkh = g_kh + bbase;
        const __half* pvh = g_vh + bbase;
        #pragma unroll
        for (int rep = 0; rep < 2; rep++) {
            int i  = tid + rep * 256;
            int r  = i >> 3, cb = i & 7;
            uint32_t so = (uint32_t)(r * 64 + ((cb ^ (r & 7)) << 3)) * 2;
            int go = r * 64 + cb * 8;
            cp_async16(sbase + 0    + so, pkh + go);
            cp_async16(sbase + 8192 + so, pvh + go);
        }
        CP_COMMIT();
    }

    for (int kt = 0; kt < nkt; kt++) {
        const int cur = kt & 1;
        const int nxt = cur ^ 1;

        // ---- prefetch tile kt+1 into other buffer ----
        if (kt + 1 < nkt) {
            const size_t tb = bbase + (size_t)(kt + 1) * 64 * HDIM;
            const __half* pkh = g_kh + tb;
            const __half* pvh = g_vh + tb;
            const uint32_t db = sbase + (uint32_t)nxt * 16384u;
            #pragma unroll
            for (int rep = 0; rep < 2; rep++) {
                int i  = tid + rep * 256;
                int r  = i >> 3, cb = i & 7;
                uint32_t so = (uint32_t)(r * 64 + ((cb ^ (r & 7)) << 3)) * 2;
                int go = r * 64 + cb * 8;
                cp_async16(db + 0    + so, pkh + go);
                cp_async16(db + 8192 + so, pvh + go);
            }
        }
        CP_COMMIT();
        CP_WAIT1();            // tile kt's group complete
        __syncthreads();

        const __half* sKh = smp + cur * 8192;
        const __half* sVh = sKh + 4096;
        const int j0 = kt * 64;

        // ---- S = Qh.Kh^T (single pass, fp32 accum, log2 domain) ----
        float sacc[8][4];
        #pragma unroll
        for (int nt = 0; nt < 8; nt++)
            #pragma unroll
            for (int c = 0; c < 4; c++) sacc[nt][c] = 0.f;

        #pragma unroll
        for (int kp = 0; kp < 2; kp++) {
            #pragma unroll
            for (int nt = 0; nt < 8; nt++) {
                int krow = nt * 8 + lr;
                int cb   = kp * 4 + mat;
                int soff = krow * 64 + ((cb ^ (krow & 7)) << 3);
                uint32_t bh[4];
                ldsm_x4(bh, smem_u32(sKh + soff));
                mma_f16(sacc[nt], aQh[2 * kp],     bh[0], bh[1]);
                mma_f16(sacc[nt], aQh[2 * kp + 1], bh[2], bh[3]);
            }
        }

        // ---- causal mask: only the two diagonal tiles need it ----
        if (kt + 2 >= nkt) {
            #pragma unroll
            for (int nt = 0; nt < 8; nt++) {
                int j = j0 + nt * 8 + tig * 2;
                sacc[nt][0] = (j     <= row0_g) ? sacc[nt][0] : NEG;
                sacc[nt][1] = (j + 1 <= row0_g) ? sacc[nt][1] : NEG;
                sacc[nt][2] = (j     <= row1_g) ? sacc[nt][2] : NEG;
                sacc[nt][3] = (j + 1 <= row1_g) ? sacc[nt][3] : NEG;
            }
        }

        // ---- online softmax (log2 domain, 2 rows/thread) ----
        float mt0 = NEG, mt1 = NEG;
        #pragma unroll
        for (int nt = 0; nt < 8; nt++) {
            mt0 = fmaxf(mt0, fmaxf(sacc[nt][0], sacc[nt][1]));
            mt1 = fmaxf(mt1, fmaxf(sacc[nt][2], sacc[nt][3]));
        }
        mt0 = fmaxf(mt0, __shfl_xor_sync(0xffffffffu, mt0, 1));
        mt0 = fmaxf(mt0, __shfl_xor_sync(0xffffffffu, mt0, 2));
        mt1 = fmaxf(mt1, __shfl_xor_sync(0xffffffffu, mt1, 1));
        mt1 = fmaxf(mt1, __shfl_xor_sync(0xffffffffu, mt1, 2));

        const float mn0 = fmaxf(m0, mt0);
        const float mn1 = fmaxf(m1, mt1);
        const float cr0 = fast_exp2(m0 - mn0);
        const float cr1 = fast_exp2(m1 - mn1);
        m0 = mn0; m1 = mn1;

        float ls0 = 0.f, ls1 = 0.f;
        #pragma unroll
        for (int nt = 0; nt < 8; nt++) {
            sacc[nt][0] = fast_exp2(sacc[nt][0] - mn0);
            sacc[nt][1] = fast_exp2(sacc[nt][1] - mn0);
            sacc[nt][2] = fast_exp2(sacc[nt][2] - mn1);
            sacc[nt][3] = fast_exp2(sacc[nt][3] - mn1);
            ls0 += sacc[nt][0] + sacc[nt][1];
            ls1 += sacc[nt][2] + sacc[nt][3];
        }
        l0 = l0 * cr0 + ls0;
        l1 = l1 * cr1 + ls1;

        #pragma unroll
        for (int nh = 0; nh < 8; nh++) {
            Oacc[nh][0] *= cr0; Oacc[nh][1] *= cr0;
            Oacc[nh][2] *= cr1; Oacc[nh][3] *= cr1;
        }

        // ---- O += P.Vh (P split: Ph + Pl passes) ----
        #pragma unroll
        for (int kc = 0; kc < 4; kc++) {
            uint32_t aPh[4], aPl[4];
            split_pair(sacc[2 * kc][0],     sacc[2 * kc][1],     aPh[0], aPl[0]);
            split_pair(sacc[2 * kc][2],     sacc[2 * kc][3],     aPh[1], aPl[1]);
            split_pair(sacc[2 * kc + 1][0], sacc[2 * kc + 1][1], aPh[2], aPl[2]);
            split_pair(sacc[2 * kc + 1][2], sacc[2 * kc + 1][3], aPh[3], aPl[3]);

            #pragma unroll
            for (int np = 0; np < 4; np++) {
                int vrow = kc * 16 + lr + ((mat & 1) << 3);
                int cb   = np * 2 + (mat >> 1);
                int soff = vrow * 64 + ((cb ^ (vrow & 7)) << 3);
                uint32_t bh[4];
                ldsm_x4_t(bh, smem_u32(sVh + soff));
                mma_f16(Oacc[2 * np],     aPh, bh[0], bh[1]);
                mma_f16(Oacc[2 * np],     aPl, bh[0], bh[1]);
                mma_f16(Oacc[2 * np + 1], aPh, bh[2], bh[3]);
                mma_f16(Oacc[2 * np + 1], aPl, bh[2], bh[3]);
            }
        }
        __syncthreads();     // buffer cur fully consumed before it is refilled
    }

    // ---- epilogue: finish row sums, normalize, store ----
    l0 += __shfl_xor_sync(0xffffffffu, l0, 1);
    l0 += __shfl_xor_sync(0xffffffffu, l0, 2);
    l1 += __shfl_xor_sync(0xffffffffu, l1, 1);
    l1 += __shfl_xor_sync(0xffffffffu, l1, 2);
    const float inv0 = 1.f / l0;
    const float inv1 = 1.f / l1;

    float* po = out + (size_t)b * SEQ * HDIM;
    #pragma unroll
    for (int nh = 0; nh < 8; nh++) {
        int c = nh * 8 + tig * 2;
        *(float2*)(po + (size_t)row0_g * HDIM + c) =
            make_float2(Oacc[nh][0] * inv0, Oacc[nh][1] * inv0);
        *(float2*)(po + (size_t)row1_g * HDIM + c) =
            make_float2(Oacc[nh][2] * inv1, Oacc[nh][3] * inv1);
    }
}

// ---------------------------------------------------------------------------
extern "C" void kernel_launch(void* const* d_in, const int* in_sizes, int n_in,
                              void* d_out, int out_size)
{
    const float* x  = (const float*)d_in[0];
    const float* Wk = (const float*)d_in[1];
    const float* Wq = (const float*)d_in[2];
    const float* Wv = (const float*)d_in[3];
    float* out = (float*)d_out;

    (void)in_sizes; (void)n_in; (void)out_size;

    cudaFuncSetAttribute(qkv_mma_kernel,
                         cudaFuncAttributeMaxDynamicSharedMemorySize, 65536);
    cudaFuncSetAttribute(attn_mma_kernel,
                         cudaFuncAttributeMaxDynamicSharedMemorySize, 32768);

    qkv_mma_kernel<<<BT / 128, 256, 65536>>>(x, Wk, Wq, Wv);
    attn_mma_kernel<<<dim3(SEQ / 128, BATCH), 256, 32768>>>(out);
}

// round 17
// speedup vs baseline: 11.0036x; 1.1519x over previous
#include <cuda_runtime.h>
#include <cuda_fp16.h>
#include <math.h>
#include <stdint.h>

// Problem constants
#define BATCH 32
#define SEQ   2048
#define CDIM  384
#define HDIM  64
#define BT    (BATCH * SEQ)

// Projected q,k,v (fp16 hi parts only; q pre-scaled by H^{-1/2}*log2(e))
__device__ __half g_qh[BT * HDIM];
__device__ __half g_kh[BT * HDIM];
__device__ __half g_vh[BT * HDIM];

// ===========================================================================
// Warp-MMA helpers (sm_80+ baseline PTX)
// ===========================================================================
__device__ __forceinline__ uint32_t smem_u32(const void* p) {
    uint32_t a;
    asm("{ .reg .u64 t; cvta.to.shared.u64 t, %1; cvt.u32.u64 %0, t; }"
        : "=r"(a) : "l"(p));
    return a;
}

__device__ __forceinline__ void ldsm_x4(uint32_t* r, uint32_t a) {
    asm volatile("ldmatrix.sync.aligned.m8n8.x4.shared.b16 {%0,%1,%2,%3}, [%4];"
                 : "=r"(r[0]), "=r"(r[1]), "=r"(r[2]), "=r"(r[3]) : "r"(a));
}
__device__ __forceinline__ void ldsm_x4_t(uint32_t* r, uint32_t a) {
    asm volatile("ldmatrix.sync.aligned.m8n8.x4.trans.shared.b16 {%0,%1,%2,%3}, [%4];"
                 : "=r"(r[0]), "=r"(r[1]), "=r"(r[2]), "=r"(r[3]) : "r"(a));
}

__device__ __forceinline__ void mma_f16(float* c, const uint32_t* a,
                                        uint32_t b0, uint32_t b1) {
    asm volatile(
        "mma.sync.aligned.m16n8k16.row.col.f32.f16.f16.f32 "
        "{%0,%1,%2,%3}, {%4,%5,%6,%7}, {%8,%9}, {%0,%1,%2,%3};"
        : "+f"(c[0]), "+f"(c[1]), "+f"(c[2]), "+f"(c[3])
        : "r"(a[0]), "r"(a[1]), "r"(a[2]), "r"(a[3]), "r"(b0), "r"(b1));
}

__device__ __forceinline__ void cp_async16(uint32_t dst, const void* src) {
    asm volatile("cp.async.cg.shared.global [%0], [%1], 16;" :: "r"(dst), "l"(src));
}
#define CP_COMMIT() asm volatile("cp.async.commit_group;" ::: "memory")
#define CP_WAIT1()  asm volatile("cp.async.wait_group 1;" ::: "memory")

__device__ __forceinline__ float fast_exp2(float x) {
    float y;
    asm("ex2.approx.ftz.f32 %0, %1;" : "=f"(y) : "f"(x));
    return y;
}

__device__ __forceinline__ uint32_t pack_h2(__half x, __half y) {
    __half2 t = __halves2half2(x, y);
    return *(uint32_t*)&t;
}

// Pack two floats into a half2 word (single cvt.rn.f16x2.f32).
__device__ __forceinline__ uint32_t pack_f2h2(float x, float y) {
    __half2 t = __float22half2_rn(make_float2(x, y));
    return *(uint32_t*)&t;
}

// Split a float pair into packed fp16 hi and lo words.
__device__ __forceinline__ void split_pair(float x, float y,
                                           uint32_t& hi, uint32_t& lo) {
    __half hx = __float2half(x);
    __half hy = __float2half(y);
    __half lx = __float2half(x - __half2float(hx));
    __half ly = __float2half(y - __half2float(hy));
    hi = pack_h2(hx, hy);
    lo = pack_h2(lx, ly);
}

// ---------------------------------------------------------------------------
// Kernel 1: fused QKV projection via fp16 HMMA, 2-pass (Xh.Wh + Xh.Wl).
// X stored hi-only in smem; W split hi/lo. Block: 256 thr / 8 warps,
// tile 128 x 192 (3 mats x 64). Epilogue: q scaled by H^{-1/2}*log2(e).
// ---------------------------------------------------------------------------
__global__ __launch_bounds__(256) void qkv_mma_kernel(
    const float* __restrict__ x,
    const float* __restrict__ Wk,
    const float* __restrict__ Wq,
    const float* __restrict__ Wv)
{
    extern __shared__ __half smp[];
    __half* sXh = smp;                 // 128 x 64 halves (8192)
    __half* sWh = smp + 8192;          // 64 x 192 halves (12288)
    __half* sWl = smp + 20480;

    const int m0   = blockIdx.x * 128;
    const int tid  = threadIdx.x;
    const int lane = tid & 31;
    const int w    = tid >> 5;
    const int wm   = w >> 1;           // 0..3
    const int wn   = w & 1;            // 0..1
    const int wrow0 = wm * 32;
    const int lr   = lane & 7;
    const int mat  = lane >> 3;
    const int g    = lane >> 2;
    const int tig  = lane & 3;

    const float* Wmat[3] = {Wq, Wk, Wv};

    float C[2][12][4];
    #pragma unroll
    for (int mt = 0; mt < 2; mt++)
        #pragma unroll
        for (int nf = 0; nf < 12; nf++)
            #pragma unroll
            for (int c = 0; c < 4; c++) C[mt][nf][c] = 0.f;

    // prefetch X chunk 0 into registers
    float4 px[8];
    #pragma unroll
    for (int rep = 0; rep < 8; rep++) {
        int id = tid + rep * 256;
        int r  = id >> 4;
        int c4 = (id & 15) * 4;
        px[rep] = *(const float4*)(x + (size_t)(m0 + r) * CDIM + c4);
    }

    for (int c = 0; c < 6; c++) {
        const int k0 = c * 64;

        // ---- STS X (hi only, swizzled) from prefetched regs ----
        #pragma unroll
        for (int rep = 0; rep < 8; rep++) {
            int id = tid + rep * 256;
            int r  = id >> 4;
            int c4 = (id & 15) * 4;
            uint32_t h01 = pack_f2h2(px[rep].x, px[rep].y);
            uint32_t h23 = pack_f2h2(px[rep].z, px[rep].w);
            int off = r * 64 + (((c4 >> 3) ^ (r & 7)) << 3) + (c4 & 7);
            *(uint2*)(sXh + off) = make_uint2(h01, h23);
        }
        // ---- LDG + STS W (split hi/lo, swizzled) ----
        #pragma unroll
        for (int mm = 0; mm < 3; mm++) {
            #pragma unroll
            for (int rep = 0; rep < 4; rep++) {
                int id = tid + rep * 256;
                int r  = id >> 4;
                int c4 = (id & 15) * 4;
                float4 v = *(const float4*)(Wmat[mm] + (size_t)(k0 + r) * HDIM + c4);
                uint32_t h01, l01, h23, l23;
                split_pair(v.x, v.y, h01, l01);
                split_pair(v.z, v.w, h23, l23);
                int colh = mm * 64 + c4;
                int off  = r * 192 + ((((colh >> 3)) ^ (r & 7)) << 3) + (colh & 7);
                *(uint2*)(sWh + off) = make_uint2(h01, h23);
                *(uint2*)(sWl + off) = make_uint2(l01, l23);
            }
        }
        __syncthreads();

        // ---- prefetch next X chunk (LDG overlapped with MMA below) ----
        if (c < 5) {
            #pragma unroll
            for (int rep = 0; rep < 8; rep++) {
                int id = tid + rep * 256;
                int r  = id >> 4;
                int c4 = (id & 15) * 4;
                px[rep] = *(const float4*)(x + (size_t)(m0 + r) * CDIM + k0 + 64 + c4);
            }
        }

        // ---- MMA: 4 k-steps of 16, 2 passes (Wh + Wl) ----
        #pragma unroll
        for (int ks = 0; ks < 4; ks++) {
            uint32_t aXh[2][4];
            #pragma unroll
            for (int mt = 0; mt < 2; mt++) {
                int arow = wrow0 + mt * 16 + lr + ((mat & 1) << 3);
                int kb   = ks * 2 + (mat >> 1);
                int aoff = arow * 64 + ((kb ^ (arow & 7)) << 3);
                ldsm_x4(aXh[mt], smem_u32(sXh + aoff));
            }
            #pragma unroll
            for (int nb = 0; nb < 6; nb++) {
                int brow = ks * 16 + lr + ((mat & 1) << 3);
                int cbg  = wn * 12 + nb * 2 + (mat >> 1);
                int boff = brow * 192 + ((cbg ^ (brow & 7)) << 3);
                uint32_t bh[4], bl[4];
                ldsm_x4_t(bh, smem_u32(sWh + boff));
                ldsm_x4_t(bl, smem_u32(sWl + boff));
                #pragma unroll
                for (int mt = 0; mt < 2; mt++) {
                    mma_f16(C[mt][2 * nb],     aXh[mt], bh[0], bh[1]);
                    mma_f16(C[mt][2 * nb],     aXh[mt], bl[0], bl[1]);
                    mma_f16(C[mt][2 * nb + 1], aXh[mt], bh[2], bh[3]);
                    mma_f16(C[mt][2 * nb + 1], aXh[mt], bl[2], bl[3]);
                }
            }
        }
        __syncthreads();
    }

    // ---- epilogue: scale q (with log2e folded), store hi parts ----
    const float QSCL = 0.125f * 1.4426950408889634f;   // H^{-1/2} * log2(e)
    #pragma unroll
    for (int mt = 0; mt < 2; mt++) {
        #pragma unroll
        for (int nf = 0; nf < 12; nf++) {
            int col = wn * 96 + nf * 8 + tig * 2;
            int mm  = col >> 6;
            int cin = col & 63;
            float s = (mm == 0) ? QSCL : 1.f;
            size_t r0 = (size_t)(m0 + wrow0 + mt * 16 + g);
            uint32_t h01 = pack_f2h2(C[mt][nf][0] * s, C[mt][nf][1] * s);
            uint32_t h23 = pack_f2h2(C[mt][nf][2] * s, C[mt][nf][3] * s);
            __half* ohp = (mm == 0) ? g_qh : ((mm == 1) ? g_kh : g_vh);
            *(uint32_t*)(ohp + r0 * 64 + cin)       = h01;
            *(uint32_t*)(ohp + (r0 + 8) * 64 + cin) = h23;
        }
    }
}

// ---------------------------------------------------------------------------
// Kernel 2: warp-MMA flash attention, cp.async double-buffered {Kh,Vh}.
// Block: 256 threads / 8 warps, 128 q-rows (16 per warp), 64-key tiles.
// S = Qh.Kh (fp32 accum, log2 domain) ; O += Ph.Vh (single pass, fp16 P).
// Causal masking applied only to the two diagonal tiles (uniform branch).
// Smem: 2 x 16KB buffers (32KB dynamic); 2 CTAs/SM forced.
// ---------------------------------------------------------------------------
__global__ __launch_bounds__(256, 2) void attn_mma_kernel(float* __restrict__ out)
{
    extern __shared__ __half smp[];
    const uint32_t sbase = smem_u32(smp);

    const int b    = blockIdx.y;
    const int qt   = (int)gridDim.x - 1 - (int)blockIdx.x;   // heavy blocks first
    const int tid  = threadIdx.x;
    const int lane = tid & 31;
    const int w    = tid >> 5;
    const int g    = lane >> 2;
    const int tig  = lane & 3;
    const int lr   = lane & 7;
    const int mat  = lane >> 3;
    const float NEG = __int_as_float(0xff800000);

    const int row0_g = qt * 128 + w * 16 + g;
    const int row1_g = row0_g + 8;

    // ---- Stage Q hi through buffer 0, preload A fragments ----
    uint32_t aQh[4][4];
    {
        __half* sQ = smp;
        const int qrow = w * 16 + lr + ((mat & 1) << 3);
        const __half* gqh = g_qh + ((size_t)b * SEQ + qt * 128) * HDIM;

        for (int i = tid; i < 128 * 8; i += 256) {
            int r = i >> 3, cb = i & 7;
            *(uint4*)(sQ + r * 64 + ((cb ^ (r & 7)) << 3)) =
                *(const uint4*)(gqh + r * 64 + (cb << 3));
        }
        __syncthreads();
        #pragma unroll
        for (int kc = 0; kc < 4; kc++) {
            int cb = kc * 2 + (mat >> 1);
            ldsm_x4(aQh[kc], smem_u32(sQ + qrow * 64 + ((cb ^ (qrow & 7)) << 3)));
        }
        __syncthreads();    // fragments read before cp.async overwrites buf0
    }

    float Oacc[8][4];
    #pragma unroll
    for (int nh = 0; nh < 8; nh++)
        #pragma unroll
        for (int c = 0; c < 4; c++) Oacc[nh][c] = 0.f;
    float m0 = NEG, m1 = NEG, l0 = 0.f, l1 = 0.f;

    const int nkt = 2 * qt + 2;
    const size_t bbase = (size_t)b * SEQ * HDIM;

    // ---- prologue: async-load tile 0 into buffer 0 ----
    {
        const __half* pkh = g_kh + bbase;
        const __half* pvh = g_vh + bbase;
        #pragma unroll
        for (int rep = 0; rep < 2; rep++) {
            int i  = tid + rep * 256;
            int r  = i >> 3, cb = i & 7;
            uint32_t so = (uint32_t)(r * 64 + ((cb ^ (r & 7)) << 3)) * 2;
            int go = r * 64 + cb * 8;
            cp_async16(sbase + 0    + so, pkh + go);
            cp_async16(sbase + 8192 + so, pvh + go);
        }
        CP_COMMIT();
    }

    for (int kt = 0; kt < nkt; kt++) {
        const int cur = kt & 1;
        const int nxt = cur ^ 1;

        // ---- prefetch tile kt+1 into other buffer ----
        if (kt + 1 < nkt) {
            const size_t tb = bbase + (size_t)(kt + 1) * 64 * HDIM;
            const __half* pkh = g_kh + tb;
            const __half* pvh = g_vh + tb;
            const uint32_t db = sbase + (uint32_t)nxt * 16384u;
            #pragma unroll
            for (int rep = 0; rep < 2; rep++) {
                int i  = tid + rep * 256;
                int r  = i >> 3, cb = i & 7;
                uint32_t so = (uint32_t)(r * 64 + ((cb ^ (r & 7)) << 3)) * 2;
                int go = r * 64 + cb * 8;
                cp_async16(db + 0    + so, pkh + go);
                cp_async16(db + 8192 + so, pvh + go);
            }
        }
        CP_COMMIT();
        CP_WAIT1();            // tile kt's group complete
        __syncthreads();

        const __half* sKh = smp + cur * 8192;
        const __half* sVh = sKh + 4096;
        const int j0 = kt * 64;

        // ---- S = Qh.Kh^T (single pass, fp32 accum, log2 domain) ----
        float sacc[8][4];
        #pragma unroll
        for (int nt = 0; nt < 8; nt++)
            #pragma unroll
            for (int c = 0; c < 4; c++) sacc[nt][c] = 0.f;

        #pragma unroll
        for (int kp = 0; kp < 2; kp++) {
            #pragma unroll
            for (int nt = 0; nt < 8; nt++) {
                int krow = nt * 8 + lr;
                int cb   = kp * 4 + mat;
                int soff = krow * 64 + ((cb ^ (krow & 7)) << 3);
                uint32_t bh[4];
                ldsm_x4(bh, smem_u32(sKh + soff));
                mma_f16(sacc[nt], aQh[2 * kp],     bh[0], bh[1]);
                mma_f16(sacc[nt], aQh[2 * kp + 1], bh[2], bh[3]);
            }
        }

        // ---- causal mask: only the two diagonal tiles need it ----
        if (kt + 2 >= nkt) {
            #pragma unroll
            for (int nt = 0; nt < 8; nt++) {
                int j = j0 + nt * 8 + tig * 2;
                sacc[nt][0] = (j     <= row0_g) ? sacc[nt][0] : NEG;
                sacc[nt][1] = (j + 1 <= row0_g) ? sacc[nt][1] : NEG;
                sacc[nt][2] = (j     <= row1_g) ? sacc[nt][2] : NEG;
                sacc[nt][3] = (j + 1 <= row1_g) ? sacc[nt][3] : NEG;
            }
        }

        // ---- online softmax (log2 domain, 2 rows/thread) ----
        float mt0 = NEG, mt1 = NEG;
        #pragma unroll
        for (int nt = 0; nt < 8; nt++) {
            mt0 = fmaxf(mt0, fmaxf(sacc[nt][0], sacc[nt][1]));
            mt1 = fmaxf(mt1, fmaxf(sacc[nt][2], sacc[nt][3]));
        }
        mt0 = fmaxf(mt0, __shfl_xor_sync(0xffffffffu, mt0, 1));
        mt0 = fmaxf(mt0, __shfl_xor_sync(0xffffffffu, mt0, 2));
        mt1 = fmaxf(mt1, __shfl_xor_sync(0xffffffffu, mt1, 1));
        mt1 = fmaxf(mt1, __shfl_xor_sync(0xffffffffu, mt1, 2));

        const float mn0 = fmaxf(m0, mt0);
        const float mn1 = fmaxf(m1, mt1);
        const float cr0 = fast_exp2(m0 - mn0);
        const float cr1 = fast_exp2(m1 - mn1);
        m0 = mn0; m1 = mn1;

        float ls0 = 0.f, ls1 = 0.f;
        #pragma unroll
        for (int nt = 0; nt < 8; nt++) {
            sacc[nt][0] = fast_exp2(sacc[nt][0] - mn0);
            sacc[nt][1] = fast_exp2(sacc[nt][1] - mn0);
            sacc[nt][2] = fast_exp2(sacc[nt][2] - mn1);
            sacc[nt][3] = fast_exp2(sacc[nt][3] - mn1);
            ls0 += sacc[nt][0] + sacc[nt][1];
            ls1 += sacc[nt][2] + sacc[nt][3];
        }
        l0 = l0 * cr0 + ls0;
        l1 = l1 * cr1 + ls1;

        #pragma unroll
        for (int nh = 0; nh < 8; nh++) {
            Oacc[nh][0] *= cr0; Oacc[nh][1] *= cr0;
            Oacc[nh][2] *= cr1; Oacc[nh][3] *= cr1;
        }

        // ---- O += Ph.Vh (single pass, P packed fp16) ----
        #pragma unroll
        for (int kc = 0; kc < 4; kc++) {
            uint32_t aPh[4];
            aPh[0] = pack_f2h2(sacc[2 * kc][0],     sacc[2 * kc][1]);
            aPh[1] = pack_f2h2(sacc[2 * kc][2],     sacc[2 * kc][3]);
            aPh[2] = pack_f2h2(sacc[2 * kc + 1][0], sacc[2 * kc + 1][1]);
            aPh[3] = pack_f2h2(sacc[2 * kc + 1][2], sacc[2 * kc + 1][3]);

            #pragma unroll
            for (int np = 0; np < 4; np++) {
                int vrow = kc * 16 + lr + ((mat & 1) << 3);
                int cb   = np * 2 + (mat >> 1);
                int soff = vrow * 64 + ((cb ^ (vrow & 7)) << 3);
                uint32_t bh[4];
                ldsm_x4_t(bh, smem_u32(sVh + soff));
                mma_f16(Oacc[2 * np],     aPh, bh[0], bh[1]);
                mma_f16(Oacc[2 * np + 1], aPh, bh[2], bh[3]);
            }
        }
        __syncthreads();     // buffer cur fully consumed before it is refilled
    }

    // ---- epilogue: finish row sums, normalize, store ----
    l0 += __shfl_xor_sync(0xffffffffu, l0, 1);
    l0 += __shfl_xor_sync(0xffffffffu, l0, 2);
    l1 += __shfl_xor_sync(0xffffffffu, l1, 1);
    l1 += __shfl_xor_sync(0xffffffffu, l1, 2);
    const float inv0 = 1.f / l0;
    const float inv1 = 1.f / l1;

    float* po = out + (size_t)b * SEQ * HDIM;
    #pragma unroll
    for (int nh = 0; nh < 8; nh++) {
        int c = nh * 8 + tig * 2;
        *(float2*)(po + (size_t)row0_g * HDIM + c) =
            make_float2(Oacc[nh][0] * inv0, Oacc[nh][1] * inv0);
        *(float2*)(po + (size_t)row1_g * HDIM + c) =
            make_float2(Oacc[nh][2] * inv1, Oacc[nh][3] * inv1);
    }
}

// ---------------------------------------------------------------------------
extern "C" void kernel_launch(void* const* d_in, const int* in_sizes, int n_in,
                              void* d_out, int out_size)
{
    const float* x  = (const float*)d_in[0];
    const float* Wk = (const float*)d_in[1];
    const float* Wq = (const float*)d_in[2];
    const float* Wv = (const float*)d_in[3];
    float* out = (float*)d_out;

    (void)in_sizes; (void)n_in; (void)out_size;

    cudaFuncSetAttribute(qkv_mma_kernel,
                         cudaFuncAttributeMaxDynamicSharedMemorySize, 65536);
    cudaFuncSetAttribute(attn_mma_kernel,
                         cudaFuncAttributeMaxDynamicSharedMemorySize, 32768);

    qkv_mma_kernel<<<BT / 128, 256, 65536>>>(x, Wk, Wq, Wv);
    attn_mma_kernel<<<dim3(SEQ / 128, BATCH), 256, 32768>>>(out);
}